// round 12
// baseline (speedup 1.0000x reference)
#include <cuda_runtime.h>
#include <cuda_fp16.h>
#include <cstdint>
#include <math.h>

// ---------------------------------------------------------------------------
// Problem dims
// ---------------------------------------------------------------------------
#define BATCH   2
#define SEQ     2048
#define TOK     (BATCH * SEQ)      // 4096
#define DIM     1024
#define HEADS   16
#define HD      64
#define HIDDEN  (4 * DIM)          // 4096
#define C3      (3 * DIM)          // 3072

// ---------------------------------------------------------------------------
// Scratch (device globals; no allocations allowed)
// ---------------------------------------------------------------------------
__device__ float  g_x1  [TOK * DIM];
__device__ __half g_qkvh[TOK * C3];
__device__ __half g_h1  [TOK * DIM];
__device__ __half g_h2  [TOK * DIM];
__device__ __half g_attn[TOK * DIM];
__device__ __half g_hid [TOK * HIDDEN];
__device__ __half g_wqkvT [C3 * DIM];
__device__ __half g_wprojT[DIM * DIM];
__device__ __half g_w1T   [HIDDEN * DIM];
__device__ __half g_w2T   [DIM * HIDDEN];

// ---------------------------------------------------------------------------
// Helpers
// ---------------------------------------------------------------------------
__device__ __forceinline__ uint32_t smem_u32(const void* p) {
    uint32_t a;
    asm("{ .reg .u64 t; cvta.to.shared.u64 t, %1; cvt.u32.u64 %0, t; }" : "=r"(a) : "l"(p));
    return a;
}
__device__ __forceinline__ float gelu_erf(float v) {
    return 0.5f * v * (1.0f + erff(v * 0.70710678118654752440f));
}
__device__ __forceinline__ uint32_t pack_f16x2(float a, float b) {
    uint32_t r;
    asm("cvt.rn.f16x2.f32 %0, %1, %2;" : "=r"(r) : "f"(b), "f"(a));
    return r;
}
__device__ __forceinline__ uint32_t hmul2(uint32_t a, uint32_t b) {
    uint32_t r;
    asm("mul.rn.f16x2 %0, %1, %2;" : "=r"(r) : "r"(a), "r"(b));
    return r;
}
__device__ __forceinline__ float ex2(float x) {
    float y;
    asm("ex2.approx.ftz.f32 %0, %1;" : "=f"(y) : "f"(x));
    return y;
}
__device__ __forceinline__ void mma_f16(
    float& d0, float& d1, float& d2, float& d3,
    uint32_t a0, uint32_t a1, uint32_t a2, uint32_t a3,
    uint32_t b0, uint32_t b1)
{
    asm volatile(
        "mma.sync.aligned.m16n8k16.row.col.f32.f16.f16.f32 "
        "{%0,%1,%2,%3}, {%4,%5,%6,%7}, {%8,%9}, {%0,%1,%2,%3};"
        : "+f"(d0), "+f"(d1), "+f"(d2), "+f"(d3)
        : "r"(a0), "r"(a1), "r"(a2), "r"(a3), "r"(b0), "r"(b1));
}
__device__ __forceinline__ void ldsm_x4(
    uint32_t& r0, uint32_t& r1, uint32_t& r2, uint32_t& r3, uint32_t addr)
{
    asm volatile("ldmatrix.sync.aligned.m8n8.x4.shared.b16 {%0,%1,%2,%3}, [%4];"
        : "=r"(r0), "=r"(r1), "=r"(r2), "=r"(r3) : "r"(addr));
}
__device__ __forceinline__ void ldsm_x4_t(
    uint32_t& r0, uint32_t& r1, uint32_t& r2, uint32_t& r3, uint32_t addr)
{
    asm volatile("ldmatrix.sync.aligned.m8n8.x4.trans.shared.b16 {%0,%1,%2,%3}, [%4];"
        : "=r"(r0), "=r"(r1), "=r"(r2), "=r"(r3) : "r"(addr));
}
__device__ __forceinline__ void cp_async16(uint32_t dst, const void* src) {
    asm volatile("cp.async.cg.shared.global [%0], [%1], 16;" :: "r"(dst), "l"(src));
}
#define CP_COMMIT asm volatile("cp.async.commit_group;")
template <int N>
__device__ __forceinline__ void cp_wait() {
    asm volatile("cp.async.wait_group %0;" :: "n"(N));
}

// ---------------------------------------------------------------------------
// fp16 GEMM: C = A @ BT^T, fp32 accum. 128x128 CTA, 8 warps (4x2),
// warp 32x64, m16n8k16, BK=32, 4-stage cp.async, ldmatrix fragments.
// EPI: 1=bias, 2=gelu, 4=residual.  HOUT: write fp16 (else fp32).
// ---------------------------------------------------------------------------
#define HB_ST 40
#define HB_STG (128 * HB_ST)
#define GEMMH_SMEM (8 * HB_STG * 2)     // 81920 bytes (4 stages x 2 operands)

template <int EPI, int HOUT>
__global__ void __launch_bounds__(256, 2) mma_gemm_h(
    const __half* __restrict__ A, const __half* __restrict__ BT,
    const float* __restrict__ bias, const float* __restrict__ R,
    void* __restrict__ Cv, int M, int N, int K)
{
    extern __shared__ __half smh[];
    __half* Asm = smh;
    __half* Bsm = smh + 4 * HB_STG;
    const uint32_t a_u32 = smem_u32(Asm);
    const uint32_t b_u32 = smem_u32(Bsm);

    const int tid = threadIdx.x;
    const int lane = tid & 31, warp = tid >> 5;
    const int wy = warp >> 1, wx = warp & 1;
    const int g = lane >> 2, t = lane & 3;
    const int bm = blockIdx.y * 128, bn = blockIdx.x * 128;

    uint32_t aoff[2], boff[4];
    #pragma unroll
    for (int mf = 0; mf < 2; mf++)
        aoff[mf] = (uint32_t)(((wy * 32 + mf * 16 + (lane & 15)) * HB_ST
                               + (lane >> 4) * 8) * 2);
    #pragma unroll
    for (int j = 0; j < 4; j++)
        boff[j] = (uint32_t)(((wx * 64 + j * 16 + ((lane >> 4) & 1) * 8 + (lane & 7)) * HB_ST
                              + ((lane >> 3) & 1) * 8) * 2);

    auto issue = [&](int s, int k0) {
        #pragma unroll
        for (int w = 0; w < 2; w++) {
            int id = w * 256 + tid;
            int r = id >> 2, c = (id & 3) << 3;
            cp_async16(a_u32 + (uint32_t)(s * HB_STG + r * HB_ST + c) * 2,
                       A + (long)(bm + r) * K + k0 + c);
        }
        #pragma unroll
        for (int w = 0; w < 2; w++) {
            int id = w * 256 + tid;
            int r = id >> 2, c = (id & 3) << 3;
            cp_async16(b_u32 + (uint32_t)(s * HB_STG + r * HB_ST + c) * 2,
                       BT + (long)(bn + r) * K + k0 + c);
        }
        CP_COMMIT;
    };

    float acc[2][8][4];
    #pragma unroll
    for (int i = 0; i < 2; i++)
        #pragma unroll
        for (int j = 0; j < 8; j++)
            #pragma unroll
            for (int e = 0; e < 4; e++) acc[i][j][e] = 0.f;

    const int NK = K >> 5;
    issue(0, 0);
    issue(1, 32);
    issue(2, 64);

    for (int it = 0; it < NK; ++it) {
        if (it <= NK - 3)      { cp_wait<2>(); }
        else if (it == NK - 2) { cp_wait<1>(); }
        else                   { cp_wait<0>(); }
        __syncthreads();
        if (it + 3 < NK) issue((it + 3) & 3, (it + 3) << 5);

        const uint32_t a_st = a_u32 + (uint32_t)((it & 3) * HB_STG) * 2;
        const uint32_t b_st = b_u32 + (uint32_t)((it & 3) * HB_STG) * 2;
        #pragma unroll
        for (int k16 = 0; k16 < 32; k16 += 16) {
            uint32_t af[2][4], bf[8][2];
            #pragma unroll
            for (int mf = 0; mf < 2; mf++)
                ldsm_x4(af[mf][0], af[mf][1], af[mf][2], af[mf][3],
                        a_st + aoff[mf] + k16 * 2);
            #pragma unroll
            for (int j = 0; j < 4; j++)
                ldsm_x4(bf[2*j][0], bf[2*j][1], bf[2*j+1][0], bf[2*j+1][1],
                        b_st + boff[j] + k16 * 2);
            #pragma unroll
            for (int mf = 0; mf < 2; mf++)
                #pragma unroll
                for (int nf = 0; nf < 8; nf++)
                    mma_f16(acc[mf][nf][0], acc[mf][nf][1],
                            acc[mf][nf][2], acc[mf][nf][3],
                            af[mf][0], af[mf][1], af[mf][2], af[mf][3],
                            bf[nf][0], bf[nf][1]);
        }
    }

    #pragma unroll
    for (int mf = 0; mf < 2; mf++) {
        const long row = bm + wy * 32 + mf * 16 + g;
        #pragma unroll
        for (int nf = 0; nf < 8; nf++) {
            const long col = bn + wx * 64 + nf * 8 + t * 2;
            float2 v0 = make_float2(acc[mf][nf][0], acc[mf][nf][1]);
            float2 v1 = make_float2(acc[mf][nf][2], acc[mf][nf][3]);
            if (EPI & 1) {
                const float2 bv = *reinterpret_cast<const float2*>(bias + col);
                v0.x += bv.x; v0.y += bv.y;
                v1.x += bv.x; v1.y += bv.y;
            }
            if (EPI & 2) {
                v0.x = gelu_erf(v0.x); v0.y = gelu_erf(v0.y);
                v1.x = gelu_erf(v1.x); v1.y = gelu_erf(v1.y);
            }
            if (EPI & 4) {
                const float2 r0 = *reinterpret_cast<const float2*>(R + row * N + col);
                const float2 r1 = *reinterpret_cast<const float2*>(R + (row + 8) * N + col);
                v0.x += r0.x; v0.y += r0.y;
                v1.x += r1.x; v1.y += r1.y;
            }
            if (HOUT) {
                __half* C = reinterpret_cast<__half*>(Cv);
                *reinterpret_cast<uint32_t*>(C + row * N + col) = pack_f16x2(v0.x, v0.y);
                *reinterpret_cast<uint32_t*>(C + (row + 8) * N + col) = pack_f16x2(v1.x, v1.y);
            } else {
                float* C = reinterpret_cast<float*>(Cv);
                *reinterpret_cast<float2*>(C + row * N + col) = v0;
                *reinterpret_cast<float2*>(C + (row + 8) * N + col) = v1;
            }
        }
    }
}

// ---------------------------------------------------------------------------
// fp16 flash attention: 128 q-rows/CTA, 8 warps x 16 rows. Q (pre-scaled) in
// registers; 128-key staging buffers (2x64-key subtiles per buffer, halved
// barrier count); K via ldmatrix, V via ldmatrix.trans; register-resident P;
// ex2.approx softmax.
// ---------------------------------------------------------------------------
#define KVST 72
#define KVROWS 128
#define KVBUF (KVROWS * KVST)           // halves per operand per buffer
#define FV_OFF (2 * KVBUF)
#define FLASH_SMEM (4 * KVBUF * 2)      // 73728 bytes

__global__ void __launch_bounds__(256, 2) flash_h(
    const __half* __restrict__ qkv, __half* __restrict__ out)
{
    extern __shared__ __half smh[];
    const uint32_t k_su = smem_u32(smh);
    const uint32_t v_su = smem_u32(smh + FV_OFF);

    const int tid = threadIdx.x;
    const int lane = tid & 31, warp = tid >> 5;
    const int g = lane >> 2, t = lane & 3;
    const int lm = lane >> 3, lr = lane & 7;
    const int b = blockIdx.y >> 4, h = blockIdx.y & 15;
    const int q0 = blockIdx.x * 128;
    const int m0 = warp * 16;
    const long base = (long)b * SEQ * C3 + h * HD;

    uint32_t koff[4];
    #pragma unroll
    for (int j = 0; j < 4; j++)
        koff[j] = (uint32_t)(((j * 16 + ((lane >> 4) & 1) * 8 + (lane & 7)) * KVST
                              + ((lane >> 3) & 1) * 8) * 2);

    // Q fragments (pre-scaled by 0.125*log2 e), 16 regs
    const float sscale = 0.125f * 1.4426950408889634f;
    const uint32_t sc2 = pack_f16x2(sscale, sscale);
    uint32_t qf[4][4];
    {
        const uint32_t* q_lo = reinterpret_cast<const uint32_t*>(
            qkv + base + (long)(q0 + m0 + g) * C3);
        const uint32_t* q_hi = reinterpret_cast<const uint32_t*>(
            qkv + base + (long)(q0 + m0 + g + 8) * C3);
        #pragma unroll
        for (int s = 0; s < 4; s++) {
            qf[s][0] = hmul2(q_lo[8 * s + t],     sc2);
            qf[s][1] = hmul2(q_hi[8 * s + t],     sc2);
            qf[s][2] = hmul2(q_lo[8 * s + t + 4], sc2);
            qf[s][3] = hmul2(q_hi[8 * s + t + 4], sc2);
        }
    }

    // 128 keys per issue
    auto issue_kv = [&](int kt, int bf) {
        const long kb = base + (long)(kt * KVROWS) * C3;
        #pragma unroll
        for (int i = 0; i < 4; i++) {
            int id = i * 256 + tid;
            int r = id >> 3, c = (id & 7) << 3;
            cp_async16(k_su + (uint32_t)(bf * KVBUF + r * KVST + c) * 2,
                       qkv + kb + (long)r * C3 + 1024 + c);
        }
        #pragma unroll
        for (int i = 0; i < 4; i++) {
            int id = i * 256 + tid;
            int r = id >> 3, c = (id & 7) << 3;
            cp_async16(v_su + (uint32_t)(bf * KVBUF + r * KVST + c) * 2,
                       qkv + kb + (long)r * C3 + 2048 + c);
        }
        CP_COMMIT;
    };

    float Of[8][4];
    #pragma unroll
    for (int nf = 0; nf < 8; nf++)
        #pragma unroll
        for (int e = 0; e < 4; e++) Of[nf][e] = 0.f;
    float m_[2] = {-1e30f, -1e30f};
    float l_[2] = {0.f, 0.f};

    issue_kv(0, 0);

    const int NT = SEQ / KVROWS;       // 16
    for (int kt = 0; kt < NT; kt++) {
        const int buf = kt & 1;
        __syncthreads();
        if (kt + 1 < NT) { issue_kv(kt + 1, buf ^ 1); cp_wait<1>(); }
        else             { cp_wait<0>(); }
        __syncthreads();

        #pragma unroll
        for (int sub = 0; sub < 2; sub++) {
            const uint32_t k_base = k_su + (uint32_t)(buf * KVBUF + sub * 64 * KVST) * 2;
            const uint32_t v_base = v_su + (uint32_t)(buf * KVBUF + sub * 64 * KVST) * 2;

            // S = Q @ K^T
            float Sf[8][4];
            #pragma unroll
            for (int nf = 0; nf < 8; nf++)
                #pragma unroll
                for (int e = 0; e < 4; e++) Sf[nf][e] = 0.f;

            #pragma unroll
            for (int s = 0; s < 4; s++) {
                uint32_t kf[8][2];
                #pragma unroll
                for (int j = 0; j < 4; j++)
                    ldsm_x4(kf[2*j][0], kf[2*j][1], kf[2*j+1][0], kf[2*j+1][1],
                            k_base + koff[j] + s * 32);
                #pragma unroll
                for (int nf = 0; nf < 8; nf++)
                    mma_f16(Sf[nf][0], Sf[nf][1], Sf[nf][2], Sf[nf][3],
                            qf[s][0], qf[s][1], qf[s][2], qf[s][3],
                            kf[nf][0], kf[nf][1]);
            }

            // Online softmax (ex2.approx)
            #pragma unroll
            for (int r = 0; r < 2; r++) {
                const int e = r * 2;
                float mx = -1e30f;
                #pragma unroll
                for (int nf = 0; nf < 8; nf++)
                    mx = fmaxf(mx, fmaxf(Sf[nf][e], Sf[nf][e + 1]));
                mx = fmaxf(mx, __shfl_xor_sync(0xffffffffu, mx, 1));
                mx = fmaxf(mx, __shfl_xor_sync(0xffffffffu, mx, 2));
                const float nm = fmaxf(m_[r], mx);
                const float corr = ex2(m_[r] - nm);
                float ps = 0.f;
                #pragma unroll
                for (int nf = 0; nf < 8; nf++) {
                    Sf[nf][e]     = ex2(Sf[nf][e] - nm);
                    Sf[nf][e + 1] = ex2(Sf[nf][e + 1] - nm);
                    ps += Sf[nf][e] + Sf[nf][e + 1];
                }
                ps += __shfl_xor_sync(0xffffffffu, ps, 1);
                ps += __shfl_xor_sync(0xffffffffu, ps, 2);
                l_[r] = l_[r] * corr + ps;
                m_[r] = nm;
                #pragma unroll
                for (int nf = 0; nf < 8; nf++) {
                    Of[nf][e] *= corr; Of[nf][e + 1] *= corr;
                }
            }

            // O += P @ V
            #pragma unroll
            for (int s = 0; s < 4; s++) {
                uint32_t pa0 = pack_f16x2(Sf[2*s][0],   Sf[2*s][1]);
                uint32_t pa1 = pack_f16x2(Sf[2*s][2],   Sf[2*s][3]);
                uint32_t pa2 = pack_f16x2(Sf[2*s+1][0], Sf[2*s+1][1]);
                uint32_t pa3 = pack_f16x2(Sf[2*s+1][2], Sf[2*s+1][3]);
                #pragma unroll
                for (int np = 0; np < 4; np++) {
                    uint32_t b0a, b1a, b0b, b1b;
                    const uint32_t addr = v_base +
                        (uint32_t)((16 * s + (lm & 1) * 8 + lr) * KVST + 16 * np + (lm >> 1) * 8) * 2;
                    ldsm_x4_t(b0a, b1a, b0b, b1b, addr);
                    mma_f16(Of[2*np][0],   Of[2*np][1],   Of[2*np][2],   Of[2*np][3],
                            pa0, pa1, pa2, pa3, b0a, b1a);
                    mma_f16(Of[2*np+1][0], Of[2*np+1][1], Of[2*np+1][2], Of[2*np+1][3],
                            pa0, pa1, pa2, pa3, b0b, b1b);
                }
            }
        }
    }

    // Normalize, write fp16 merged heads
    #pragma unroll
    for (int r = 0; r < 2; r++) {
        const float inv = 1.0f / l_[r];
        const long row = (long)b * SEQ + q0 + m0 + g + r * 8;
        const int e = r * 2;
        #pragma unroll
        for (int nf = 0; nf < 8; nf++) {
            *reinterpret_cast<uint32_t*>(out + row * DIM + h * HD + nf * 8 + 2 * t) =
                pack_f16x2(Of[nf][e] * inv, Of[nf][e + 1] * inv);
        }
    }
}

// ---------------------------------------------------------------------------
// Weight transpose + fp16 convert
// ---------------------------------------------------------------------------
__global__ void __launch_bounds__(256) cvt_T(
    const float* __restrict__ in, __half* __restrict__ out, int Rr, int Cc)
{
    __shared__ float tb[32][33];
    const int c0 = blockIdx.x * 32, r0 = blockIdx.y * 32;
    const int x = threadIdx.x & 31, y = (threadIdx.x >> 5) * 4;
    #pragma unroll
    for (int i = 0; i < 4; i++)
        tb[y + i][x] = in[(long)(r0 + y + i) * Cc + c0 + x];
    __syncthreads();
    #pragma unroll
    for (int i = 0; i < 4; i++)
        out[(long)(c0 + y + i) * Rr + r0 + x] = __float2half(tb[x][y + i]);
}

// ---------------------------------------------------------------------------
// LayerNorm -> fp16
// ---------------------------------------------------------------------------
__global__ void __launch_bounds__(256) ln_h_kernel(
    const float* __restrict__ x, const float* __restrict__ g,
    const float* __restrict__ b, __half* __restrict__ out)
{
    const int row = blockIdx.x;
    const int tid = threadIdx.x;
    float4 v = reinterpret_cast<const float4*>(x + (long)row * DIM)[tid];

    __shared__ float red1[8];
    __shared__ float red2[8];

    float s = v.x + v.y + v.z + v.w;
    #pragma unroll
    for (int off = 16; off; off >>= 1) s += __shfl_xor_sync(0xffffffffu, s, off);
    if ((tid & 31) == 0) red1[tid >> 5] = s;
    __syncthreads();
    float tot = 0.f;
    #pragma unroll
    for (int w = 0; w < 8; w++) tot += red1[w];
    const float mean = tot * (1.0f / DIM);

    float dx = v.x - mean, dy = v.y - mean, dz = v.z - mean, dw = v.w - mean;
    float q = dx * dx + dy * dy + dz * dz + dw * dw;
    #pragma unroll
    for (int off = 16; off; off >>= 1) q += __shfl_xor_sync(0xffffffffu, q, off);
    if ((tid & 31) == 0) red2[tid >> 5] = q;
    __syncthreads();
    float qtot = 0.f;
    #pragma unroll
    for (int w = 0; w < 8; w++) qtot += red2[w];
    const float rstd = rsqrtf(qtot * (1.0f / DIM) + 1e-5f);

    float4 gv = reinterpret_cast<const float4*>(g)[tid];
    float4 bv = reinterpret_cast<const float4*>(b)[tid];
    uint32_t* op = reinterpret_cast<uint32_t*>(out + (long)row * DIM) + 2 * tid;
    op[0] = pack_f16x2(dx * rstd * gv.x + bv.x, dy * rstd * gv.y + bv.y);
    op[1] = pack_f16x2(dz * rstd * gv.z + bv.z, dw * rstd * gv.w + bv.w);
}

// ---------------------------------------------------------------------------
// Launch
// ---------------------------------------------------------------------------
extern "C" void kernel_launch(void* const* d_in, const int* in_sizes, int n_in,
                              void* d_out, int out_size)
{
    const float* x      = (const float*)d_in[0];
    const float* ln1_g  = (const float*)d_in[1];
    const float* ln1_b  = (const float*)d_in[2];
    const float* w_qkv  = (const float*)d_in[3];
    const float* w_proj = (const float*)d_in[4];
    const float* b_proj = (const float*)d_in[5];
    const float* ln2_g  = (const float*)d_in[6];
    const float* ln2_b  = (const float*)d_in[7];
    const float* w1     = (const float*)d_in[8];
    const float* b1     = (const float*)d_in[9];
    const float* w2     = (const float*)d_in[10];
    const float* b2     = (const float*)d_in[11];
    float* out = (float*)d_out;

    float *x1;
    __half *qkvh, *h1, *h2, *attn, *hid, *wqkvT, *wprojT, *w1T, *w2T;
    cudaGetSymbolAddress((void**)&x1,     g_x1);
    cudaGetSymbolAddress((void**)&qkvh,   g_qkvh);
    cudaGetSymbolAddress((void**)&h1,     g_h1);
    cudaGetSymbolAddress((void**)&h2,     g_h2);
    cudaGetSymbolAddress((void**)&attn,   g_attn);
    cudaGetSymbolAddress((void**)&hid,    g_hid);
    cudaGetSymbolAddress((void**)&wqkvT,  g_wqkvT);
    cudaGetSymbolAddress((void**)&wprojT, g_wprojT);
    cudaGetSymbolAddress((void**)&w1T,    g_w1T);
    cudaGetSymbolAddress((void**)&w2T,    g_w2T);

    cudaFuncSetAttribute(mma_gemm_h<0,1>, cudaFuncAttributeMaxDynamicSharedMemorySize, GEMMH_SMEM);
    cudaFuncSetAttribute(mma_gemm_h<5,0>, cudaFuncAttributeMaxDynamicSharedMemorySize, GEMMH_SMEM);
    cudaFuncSetAttribute(mma_gemm_h<3,1>, cudaFuncAttributeMaxDynamicSharedMemorySize, GEMMH_SMEM);
    cudaFuncSetAttribute(flash_h,         cudaFuncAttributeMaxDynamicSharedMemorySize, FLASH_SMEM);

    // Weight transposes -> fp16 k-major [N][K]
    cvt_T<<<dim3(C3 / 32,     DIM / 32),    256>>>(w_qkv,  wqkvT,  DIM,    C3);
    cvt_T<<<dim3(DIM / 32,    DIM / 32),    256>>>(w_proj, wprojT, DIM,    DIM);
    cvt_T<<<dim3(HIDDEN / 32, DIM / 32),    256>>>(w1,     w1T,    DIM,    HIDDEN);
    cvt_T<<<dim3(DIM / 32,    HIDDEN / 32), 256>>>(w2,     w2T,    HIDDEN, DIM);

    // 1) h1 = LN1(x)  (fp16)
    ln_h_kernel<<<TOK, 256>>>(x, ln1_g, ln1_b, h1);

    // 2) qkvh = h1 @ w_qkv  (fp16 out)
    mma_gemm_h<0,1><<<dim3(C3 / 128, TOK / 128), 256, GEMMH_SMEM>>>(
        h1, wqkvT, nullptr, nullptr, qkvh, TOK, C3, DIM);

    // 3) attention
    flash_h<<<dim3(SEQ / 128, BATCH * HEADS), 256, FLASH_SMEM>>>(qkvh, attn);

    // 4) x1 = x + attn @ w_proj + b_proj  (fp32 residual)
    mma_gemm_h<5,0><<<dim3(DIM / 128, TOK / 128), 256, GEMMH_SMEM>>>(
        attn, wprojT, b_proj, x, x1, TOK, DIM, DIM);

    // 5) h2 = LN2(x1)  (fp16)
    ln_h_kernel<<<TOK, 256>>>(x1, ln2_g, ln2_b, h2);

    // 6) hid = gelu(h2 @ w1 + b1)  (fp16 out)
    mma_gemm_h<3,1><<<dim3(HIDDEN / 128, TOK / 128), 256, GEMMH_SMEM>>>(
        h2, w1T, b1, nullptr, hid, TOK, HIDDEN, DIM);

    // 7) out = x1 + hid @ w2 + b2  (fp32 residual)
    mma_gemm_h<5,0><<<dim3(DIM / 128, TOK / 128), 256, GEMMH_SMEM>>>(
        hid, w2T, b2, x1, out, TOK, DIM, HIDDEN);
}

// round 13
// speedup vs baseline: 1.0284x; 1.0284x over previous
#include <cuda_runtime.h>
#include <cuda_fp16.h>
#include <cstdint>
#include <math.h>

// ---------------------------------------------------------------------------
// Problem dims
// ---------------------------------------------------------------------------
#define BATCH   2
#define SEQ     2048
#define TOK     (BATCH * SEQ)      // 4096
#define DIM     1024
#define HEADS   16
#define HD      64
#define HIDDEN  (4 * DIM)          // 4096
#define C3      (3 * DIM)          // 3072

// ---------------------------------------------------------------------------
// Scratch (device globals; no allocations allowed)
// ---------------------------------------------------------------------------
__device__ float  g_x1  [TOK * DIM];
__device__ __half g_qkvh[TOK * C3];
__device__ __half g_h1  [TOK * DIM];
__device__ __half g_h2  [TOK * DIM];
__device__ __half g_attn[TOK * DIM];
__device__ __half g_hid [TOK * HIDDEN];
__device__ __half g_wqkvT [C3 * DIM];
__device__ __half g_wprojT[DIM * DIM];
__device__ __half g_w1T   [HIDDEN * DIM];
__device__ __half g_w2T   [DIM * HIDDEN];

// ---------------------------------------------------------------------------
// Helpers
// ---------------------------------------------------------------------------
__device__ __forceinline__ uint32_t smem_u32(const void* p) {
    uint32_t a;
    asm("{ .reg .u64 t; cvta.to.shared.u64 t, %1; cvt.u32.u64 %0, t; }" : "=r"(a) : "l"(p));
    return a;
}
__device__ __forceinline__ float gelu_erf(float v) {
    return 0.5f * v * (1.0f + erff(v * 0.70710678118654752440f));
}
__device__ __forceinline__ uint32_t pack_f16x2(float a, float b) {
    uint32_t r;
    asm("cvt.rn.f16x2.f32 %0, %1, %2;" : "=r"(r) : "f"(b), "f"(a));
    return r;
}
__device__ __forceinline__ uint32_t hmul2(uint32_t a, uint32_t b) {
    uint32_t r;
    asm("mul.rn.f16x2 %0, %1, %2;" : "=r"(r) : "r"(a), "r"(b));
    return r;
}
__device__ __forceinline__ uint32_t hsub2(uint32_t a, uint32_t b) {
    uint32_t r;
    asm("sub.rn.f16x2 %0, %1, %2;" : "=r"(r) : "r"(a), "r"(b));
    return r;
}
__device__ __forceinline__ uint32_t hex2x2(uint32_t a) {
    uint32_t r;
    asm("ex2.approx.f16x2 %0, %1;" : "=r"(r) : "r"(a));
    return r;
}
__device__ __forceinline__ float ex2(float x) {
    float y;
    asm("ex2.approx.ftz.f32 %0, %1;" : "=f"(y) : "f"(x));
    return y;
}
__device__ __forceinline__ float2 unpack_h2(uint32_t u) {
    __half2 h = *reinterpret_cast<__half2*>(&u);
    return __half22float2(h);
}
__device__ __forceinline__ void mma_f16(
    float& d0, float& d1, float& d2, float& d3,
    uint32_t a0, uint32_t a1, uint32_t a2, uint32_t a3,
    uint32_t b0, uint32_t b1)
{
    asm volatile(
        "mma.sync.aligned.m16n8k16.row.col.f32.f16.f16.f32 "
        "{%0,%1,%2,%3}, {%4,%5,%6,%7}, {%8,%9}, {%0,%1,%2,%3};"
        : "+f"(d0), "+f"(d1), "+f"(d2), "+f"(d3)
        : "r"(a0), "r"(a1), "r"(a2), "r"(a3), "r"(b0), "r"(b1));
}
__device__ __forceinline__ void ldsm_x4(
    uint32_t& r0, uint32_t& r1, uint32_t& r2, uint32_t& r3, uint32_t addr)
{
    asm volatile("ldmatrix.sync.aligned.m8n8.x4.shared.b16 {%0,%1,%2,%3}, [%4];"
        : "=r"(r0), "=r"(r1), "=r"(r2), "=r"(r3) : "r"(addr));
}
__device__ __forceinline__ void ldsm_x4_t(
    uint32_t& r0, uint32_t& r1, uint32_t& r2, uint32_t& r3, uint32_t addr)
{
    asm volatile("ldmatrix.sync.aligned.m8n8.x4.trans.shared.b16 {%0,%1,%2,%3}, [%4];"
        : "=r"(r0), "=r"(r1), "=r"(r2), "=r"(r3) : "r"(addr));
}
__device__ __forceinline__ void cp_async16(uint32_t dst, const void* src) {
    asm volatile("cp.async.cg.shared.global [%0], [%1], 16;" :: "r"(dst), "l"(src));
}
#define CP_COMMIT asm volatile("cp.async.commit_group;")
template <int N>
__device__ __forceinline__ void cp_wait() {
    asm volatile("cp.async.wait_group %0;" :: "n"(N));
}

// ---------------------------------------------------------------------------
// fp16 GEMM (R11 config): C = A @ BT^T, fp32 accum. 128x128 CTA, 8 warps
// (4x2), warp 32x64, m16n8k16, BK=32, 3-stage cp.async, ldmatrix fragments.
// EPI: 1=bias, 2=gelu, 4=residual.  HOUT: write fp16 (else fp32).
// ---------------------------------------------------------------------------
#define HB_ST 40
#define HB_STG (128 * HB_ST)
#define GEMMH_SMEM (6 * HB_STG * 2)     // 61440 bytes

template <int EPI, int HOUT>
__global__ void __launch_bounds__(256, 2) mma_gemm_h(
    const __half* __restrict__ A, const __half* __restrict__ BT,
    const float* __restrict__ bias, const float* __restrict__ R,
    void* __restrict__ Cv, int M, int N, int K)
{
    extern __shared__ __half smh[];
    __half* Asm = smh;
    __half* Bsm = smh + 3 * HB_STG;
    const uint32_t a_u32 = smem_u32(Asm);
    const uint32_t b_u32 = smem_u32(Bsm);

    const int tid = threadIdx.x;
    const int lane = tid & 31, warp = tid >> 5;
    const int wy = warp >> 1, wx = warp & 1;
    const int g = lane >> 2, t = lane & 3;
    const int bm = blockIdx.y * 128, bn = blockIdx.x * 128;

    uint32_t aoff[2], boff[4];
    #pragma unroll
    for (int mf = 0; mf < 2; mf++)
        aoff[mf] = (uint32_t)(((wy * 32 + mf * 16 + (lane & 15)) * HB_ST
                               + (lane >> 4) * 8) * 2);
    #pragma unroll
    for (int j = 0; j < 4; j++)
        boff[j] = (uint32_t)(((wx * 64 + j * 16 + ((lane >> 4) & 1) * 8 + (lane & 7)) * HB_ST
                              + ((lane >> 3) & 1) * 8) * 2);

    auto issue = [&](int s, int k0) {
        #pragma unroll
        for (int w = 0; w < 2; w++) {
            int id = w * 256 + tid;
            int r = id >> 2, c = (id & 3) << 3;
            cp_async16(a_u32 + (uint32_t)(s * HB_STG + r * HB_ST + c) * 2,
                       A + (long)(bm + r) * K + k0 + c);
        }
        #pragma unroll
        for (int w = 0; w < 2; w++) {
            int id = w * 256 + tid;
            int r = id >> 2, c = (id & 3) << 3;
            cp_async16(b_u32 + (uint32_t)(s * HB_STG + r * HB_ST + c) * 2,
                       BT + (long)(bn + r) * K + k0 + c);
        }
        CP_COMMIT;
    };

    float acc[2][8][4];
    #pragma unroll
    for (int i = 0; i < 2; i++)
        #pragma unroll
        for (int j = 0; j < 8; j++)
            #pragma unroll
            for (int e = 0; e < 4; e++) acc[i][j][e] = 0.f;

    const int NK = K >> 5;
    issue(0, 0);
    issue(1, 32);

    for (int it = 0; it < NK; ++it) {
        if (it == NK - 1) { cp_wait<0>(); } else { cp_wait<1>(); }
        __syncthreads();
        if (it + 2 < NK) issue((it + 2) % 3, (it + 2) << 5);

        const uint32_t a_st = a_u32 + (uint32_t)((it % 3) * HB_STG) * 2;
        const uint32_t b_st = b_u32 + (uint32_t)((it % 3) * HB_STG) * 2;
        #pragma unroll
        for (int k16 = 0; k16 < 32; k16 += 16) {
            uint32_t af[2][4], bf[8][2];
            #pragma unroll
            for (int mf = 0; mf < 2; mf++)
                ldsm_x4(af[mf][0], af[mf][1], af[mf][2], af[mf][3],
                        a_st + aoff[mf] + k16 * 2);
            #pragma unroll
            for (int j = 0; j < 4; j++)
                ldsm_x4(bf[2*j][0], bf[2*j][1], bf[2*j+1][0], bf[2*j+1][1],
                        b_st + boff[j] + k16 * 2);
            #pragma unroll
            for (int mf = 0; mf < 2; mf++)
                #pragma unroll
                for (int nf = 0; nf < 8; nf++)
                    mma_f16(acc[mf][nf][0], acc[mf][nf][1],
                            acc[mf][nf][2], acc[mf][nf][3],
                            af[mf][0], af[mf][1], af[mf][2], af[mf][3],
                            bf[nf][0], bf[nf][1]);
        }
    }

    #pragma unroll
    for (int mf = 0; mf < 2; mf++) {
        const long row = bm + wy * 32 + mf * 16 + g;
        #pragma unroll
        for (int nf = 0; nf < 8; nf++) {
            const long col = bn + wx * 64 + nf * 8 + t * 2;
            float2 v0 = make_float2(acc[mf][nf][0], acc[mf][nf][1]);
            float2 v1 = make_float2(acc[mf][nf][2], acc[mf][nf][3]);
            if (EPI & 1) {
                const float2 bv = *reinterpret_cast<const float2*>(bias + col);
                v0.x += bv.x; v0.y += bv.y;
                v1.x += bv.x; v1.y += bv.y;
            }
            if (EPI & 2) {
                v0.x = gelu_erf(v0.x); v0.y = gelu_erf(v0.y);
                v1.x = gelu_erf(v1.x); v1.y = gelu_erf(v1.y);
            }
            if (EPI & 4) {
                const float2 r0 = *reinterpret_cast<const float2*>(R + row * N + col);
                const float2 r1 = *reinterpret_cast<const float2*>(R + (row + 8) * N + col);
                v0.x += r0.x; v0.y += r0.y;
                v1.x += r1.x; v1.y += r1.y;
            }
            if (HOUT) {
                __half* C = reinterpret_cast<__half*>(Cv);
                *reinterpret_cast<uint32_t*>(C + row * N + col) = pack_f16x2(v0.x, v0.y);
                *reinterpret_cast<uint32_t*>(C + (row + 8) * N + col) = pack_f16x2(v1.x, v1.y);
            } else {
                float* C = reinterpret_cast<float*>(Cv);
                *reinterpret_cast<float2*>(C + row * N + col) = v0;
                *reinterpret_cast<float2*>(C + (row + 8) * N + col) = v1;
            }
        }
    }
}

// ---------------------------------------------------------------------------
// fp16 flash attention: 128 q-rows/CTA, 8 warps x 16 rows. Q (pre-scaled) in
// registers; 128-key staging buffers; K via ldmatrix, V via ldmatrix.trans;
// register-resident P; fp16x2 exp softmax (halved MUFU count).
// ---------------------------------------------------------------------------
#define KVST 72
#define KVROWS 128
#define KVBUF (KVROWS * KVST)
#define FV_OFF (2 * KVBUF)
#define FLASH_SMEM (4 * KVBUF * 2)      // 73728 bytes

__global__ void __launch_bounds__(256, 2) flash_h(
    const __half* __restrict__ qkv, __half* __restrict__ out)
{
    extern __shared__ __half smh[];
    const uint32_t k_su = smem_u32(smh);
    const uint32_t v_su = smem_u32(smh + FV_OFF);

    const int tid = threadIdx.x;
    const int lane = tid & 31, warp = tid >> 5;
    const int g = lane >> 2, t = lane & 3;
    const int lm = lane >> 3, lr = lane & 7;
    const int b = blockIdx.y >> 4, h = blockIdx.y & 15;
    const int q0 = blockIdx.x * 128;
    const int m0 = warp * 16;
    const long base = (long)b * SEQ * C3 + h * HD;

    uint32_t koff[4];
    #pragma unroll
    for (int j = 0; j < 4; j++)
        koff[j] = (uint32_t)(((j * 16 + ((lane >> 4) & 1) * 8 + (lane & 7)) * KVST
                              + ((lane >> 3) & 1) * 8) * 2);

    // Q fragments (pre-scaled by 0.125*log2 e)
    const float sscale = 0.125f * 1.4426950408889634f;
    const uint32_t sc2 = pack_f16x2(sscale, sscale);
    uint32_t qf[4][4];
    {
        const uint32_t* q_lo = reinterpret_cast<const uint32_t*>(
            qkv + base + (long)(q0 + m0 + g) * C3);
        const uint32_t* q_hi = reinterpret_cast<const uint32_t*>(
            qkv + base + (long)(q0 + m0 + g + 8) * C3);
        #pragma unroll
        for (int s = 0; s < 4; s++) {
            qf[s][0] = hmul2(q_lo[8 * s + t],     sc2);
            qf[s][1] = hmul2(q_hi[8 * s + t],     sc2);
            qf[s][2] = hmul2(q_lo[8 * s + t + 4], sc2);
            qf[s][3] = hmul2(q_hi[8 * s + t + 4], sc2);
        }
    }

    auto issue_kv = [&](int kt, int bf) {
        const long kb = base + (long)(kt * KVROWS) * C3;
        #pragma unroll
        for (int i = 0; i < 4; i++) {
            int id = i * 256 + tid;
            int r = id >> 3, c = (id & 7) << 3;
            cp_async16(k_su + (uint32_t)(bf * KVBUF + r * KVST + c) * 2,
                       qkv + kb + (long)r * C3 + 1024 + c);
        }
        #pragma unroll
        for (int i = 0; i < 4; i++) {
            int id = i * 256 + tid;
            int r = id >> 3, c = (id & 7) << 3;
            cp_async16(v_su + (uint32_t)(bf * KVBUF + r * KVST + c) * 2,
                       qkv + kb + (long)r * C3 + 2048 + c);
        }
        CP_COMMIT;
    };

    float Of[8][4];
    #pragma unroll
    for (int nf = 0; nf < 8; nf++)
        #pragma unroll
        for (int e = 0; e < 4; e++) Of[nf][e] = 0.f;
    float m_[2] = {-1e30f, -1e30f};
    float l_[2] = {0.f, 0.f};

    issue_kv(0, 0);

    const int NT = SEQ / KVROWS;       // 16
    for (int kt = 0; kt < NT; kt++) {
        const int buf = kt & 1;
        __syncthreads();
        if (kt + 1 < NT) { issue_kv(kt + 1, buf ^ 1); cp_wait<1>(); }
        else             { cp_wait<0>(); }
        __syncthreads();

        #pragma unroll
        for (int sub = 0; sub < 2; sub++) {
            const uint32_t k_base = k_su + (uint32_t)(buf * KVBUF + sub * 64 * KVST) * 2;
            const uint32_t v_base = v_su + (uint32_t)(buf * KVBUF + sub * 64 * KVST) * 2;

            // S = Q @ K^T
            float Sf[8][4];
            #pragma unroll
            for (int nf = 0; nf < 8; nf++)
                #pragma unroll
                for (int e = 0; e < 4; e++) Sf[nf][e] = 0.f;

            #pragma unroll
            for (int s = 0; s < 4; s++) {
                uint32_t kf[8][2];
                #pragma unroll
                for (int j = 0; j < 4; j++)
                    ldsm_x4(kf[2*j][0], kf[2*j][1], kf[2*j+1][0], kf[2*j+1][1],
                            k_base + koff[j] + s * 32);
                #pragma unroll
                for (int nf = 0; nf < 8; nf++)
                    mma_f16(Sf[nf][0], Sf[nf][1], Sf[nf][2], Sf[nf][3],
                            qf[s][0], qf[s][1], qf[s][2], qf[s][3],
                            kf[nf][0], kf[nf][1]);
            }

            // Online softmax: exp in fp16x2 (P is fp16 for PV anyway)
            uint32_t p2_[2][8];
            #pragma unroll
            for (int r = 0; r < 2; r++) {
                const int e = r * 2;
                float mx = -1e30f;
                #pragma unroll
                for (int nf = 0; nf < 8; nf++)
                    mx = fmaxf(mx, fmaxf(Sf[nf][e], Sf[nf][e + 1]));
                mx = fmaxf(mx, __shfl_xor_sync(0xffffffffu, mx, 1));
                mx = fmaxf(mx, __shfl_xor_sync(0xffffffffu, mx, 2));
                const float nm = fmaxf(m_[r], mx);
                const float corr = ex2(m_[r] - nm);
                const uint32_t nm2 = pack_f16x2(nm, nm);
                float ps = 0.f;
                #pragma unroll
                for (int nf = 0; nf < 8; nf++) {
                    uint32_t s2 = pack_f16x2(Sf[nf][e], Sf[nf][e + 1]);
                    uint32_t p = hex2x2(hsub2(s2, nm2));
                    p2_[r][nf] = p;
                    float2 pf = unpack_h2(p);
                    ps += pf.x + pf.y;
                }
                ps += __shfl_xor_sync(0xffffffffu, ps, 1);
                ps += __shfl_xor_sync(0xffffffffu, ps, 2);
                l_[r] = l_[r] * corr + ps;
                m_[r] = nm;
                #pragma unroll
                for (int nf = 0; nf < 8; nf++) {
                    Of[nf][e] *= corr; Of[nf][e + 1] *= corr;
                }
            }

            // O += P @ V (P already fp16x2 in A-fragment layout)
            #pragma unroll
            for (int s = 0; s < 4; s++) {
                const uint32_t pa0 = p2_[0][2*s];
                const uint32_t pa1 = p2_[1][2*s];
                const uint32_t pa2 = p2_[0][2*s+1];
                const uint32_t pa3 = p2_[1][2*s+1];
                #pragma unroll
                for (int np = 0; np < 4; np++) {
                    uint32_t b0a, b1a, b0b, b1b;
                    const uint32_t addr = v_base +
                        (uint32_t)((16 * s + (lm & 1) * 8 + lr) * KVST + 16 * np + (lm >> 1) * 8) * 2;
                    ldsm_x4_t(b0a, b1a, b0b, b1b, addr);
                    mma_f16(Of[2*np][0],   Of[2*np][1],   Of[2*np][2],   Of[2*np][3],
                            pa0, pa1, pa2, pa3, b0a, b1a);
                    mma_f16(Of[2*np+1][0], Of[2*np+1][1], Of[2*np+1][2], Of[2*np+1][3],
                            pa0, pa1, pa2, pa3, b0b, b1b);
                }
            }
        }
    }

    // Normalize, write fp16 merged heads
    #pragma unroll
    for (int r = 0; r < 2; r++) {
        const float inv = 1.0f / l_[r];
        const long row = (long)b * SEQ + q0 + m0 + g + r * 8;
        const int e = r * 2;
        #pragma unroll
        for (int nf = 0; nf < 8; nf++) {
            *reinterpret_cast<uint32_t*>(out + row * DIM + h * HD + nf * 8 + 2 * t) =
                pack_f16x2(Of[nf][e] * inv, Of[nf][e + 1] * inv);
        }
    }
}

// ---------------------------------------------------------------------------
// Weight transpose + fp16 convert
// ---------------------------------------------------------------------------
__global__ void __launch_bounds__(256) cvt_T(
    const float* __restrict__ in, __half* __restrict__ out, int Rr, int Cc)
{
    __shared__ float tb[32][33];
    const int c0 = blockIdx.x * 32, r0 = blockIdx.y * 32;
    const int x = threadIdx.x & 31, y = (threadIdx.x >> 5) * 4;
    #pragma unroll
    for (int i = 0; i < 4; i++)
        tb[y + i][x] = in[(long)(r0 + y + i) * Cc + c0 + x];
    __syncthreads();
    #pragma unroll
    for (int i = 0; i < 4; i++)
        out[(long)(c0 + y + i) * Rr + r0 + x] = __float2half(tb[x][y + i]);
}

// ---------------------------------------------------------------------------
// LayerNorm -> fp16
// ---------------------------------------------------------------------------
__global__ void __launch_bounds__(256) ln_h_kernel(
    const float* __restrict__ x, const float* __restrict__ g,
    const float* __restrict__ b, __half* __restrict__ out)
{
    const int row = blockIdx.x;
    const int tid = threadIdx.x;
    float4 v = reinterpret_cast<const float4*>(x + (long)row * DIM)[tid];

    __shared__ float red1[8];
    __shared__ float red2[8];

    float s = v.x + v.y + v.z + v.w;
    #pragma unroll
    for (int off = 16; off; off >>= 1) s += __shfl_xor_sync(0xffffffffu, s, off);
    if ((tid & 31) == 0) red1[tid >> 5] = s;
    __syncthreads();
    float tot = 0.f;
    #pragma unroll
    for (int w = 0; w < 8; w++) tot += red1[w];
    const float mean = tot * (1.0f / DIM);

    float dx = v.x - mean, dy = v.y - mean, dz = v.z - mean, dw = v.w - mean;
    float q = dx * dx + dy * dy + dz * dz + dw * dw;
    #pragma unroll
    for (int off = 16; off; off >>= 1) q += __shfl_xor_sync(0xffffffffu, q, off);
    if ((tid & 31) == 0) red2[tid >> 5] = q;
    __syncthreads();
    float qtot = 0.f;
    #pragma unroll
    for (int w = 0; w < 8; w++) qtot += red2[w];
    const float rstd = rsqrtf(qtot * (1.0f / DIM) + 1e-5f);

    float4 gv = reinterpret_cast<const float4*>(g)[tid];
    float4 bv = reinterpret_cast<const float4*>(b)[tid];
    uint32_t* op = reinterpret_cast<uint32_t*>(out + (long)row * DIM) + 2 * tid;
    op[0] = pack_f16x2(dx * rstd * gv.x + bv.x, dy * rstd * gv.y + bv.y);
    op[1] = pack_f16x2(dz * rstd * gv.z + bv.z, dw * rstd * gv.w + bv.w);
}

// ---------------------------------------------------------------------------
// Launch
// ---------------------------------------------------------------------------
extern "C" void kernel_launch(void* const* d_in, const int* in_sizes, int n_in,
                              void* d_out, int out_size)
{
    const float* x      = (const float*)d_in[0];
    const float* ln1_g  = (const float*)d_in[1];
    const float* ln1_b  = (const float*)d_in[2];
    const float* w_qkv  = (const float*)d_in[3];
    const float* w_proj = (const float*)d_in[4];
    const float* b_proj = (const float*)d_in[5];
    const float* ln2_g  = (const float*)d_in[6];
    const float* ln2_b  = (const float*)d_in[7];
    const float* w1     = (const float*)d_in[8];
    const float* b1     = (const float*)d_in[9];
    const float* w2     = (const float*)d_in[10];
    const float* b2     = (const float*)d_in[11];
    float* out = (float*)d_out;

    float *x1;
    __half *qkvh, *h1, *h2, *attn, *hid, *wqkvT, *wprojT, *w1T, *w2T;
    cudaGetSymbolAddress((void**)&x1,     g_x1);
    cudaGetSymbolAddress((void**)&qkvh,   g_qkvh);
    cudaGetSymbolAddress((void**)&h1,     g_h1);
    cudaGetSymbolAddress((void**)&h2,     g_h2);
    cudaGetSymbolAddress((void**)&attn,   g_attn);
    cudaGetSymbolAddress((void**)&hid,    g_hid);
    cudaGetSymbolAddress((void**)&wqkvT,  g_wqkvT);
    cudaGetSymbolAddress((void**)&wprojT, g_wprojT);
    cudaGetSymbolAddress((void**)&w1T,    g_w1T);
    cudaGetSymbolAddress((void**)&w2T,    g_w2T);

    cudaFuncSetAttribute(mma_gemm_h<0,1>, cudaFuncAttributeMaxDynamicSharedMemorySize, GEMMH_SMEM);
    cudaFuncSetAttribute(mma_gemm_h<5,0>, cudaFuncAttributeMaxDynamicSharedMemorySize, GEMMH_SMEM);
    cudaFuncSetAttribute(mma_gemm_h<3,1>, cudaFuncAttributeMaxDynamicSharedMemorySize, GEMMH_SMEM);
    cudaFuncSetAttribute(flash_h,         cudaFuncAttributeMaxDynamicSharedMemorySize, FLASH_SMEM);

    // Weight transposes -> fp16 k-major [N][K]
    cvt_T<<<dim3(C3 / 32,     DIM / 32),    256>>>(w_qkv,  wqkvT,  DIM,    C3);
    cvt_T<<<dim3(DIM / 32,    DIM / 32),    256>>>(w_proj, wprojT, DIM,    DIM);
    cvt_T<<<dim3(HIDDEN / 32, DIM / 32),    256>>>(w1,     w1T,    DIM,    HIDDEN);
    cvt_T<<<dim3(DIM / 32,    HIDDEN / 32), 256>>>(w2,     w2T,    HIDDEN, DIM);

    // 1) h1 = LN1(x)  (fp16)
    ln_h_kernel<<<TOK, 256>>>(x, ln1_g, ln1_b, h1);

    // 2) qkvh = h1 @ w_qkv  (fp16 out)
    mma_gemm_h<0,1><<<dim3(C3 / 128, TOK / 128), 256, GEMMH_SMEM>>>(
        h1, wqkvT, nullptr, nullptr, qkvh, TOK, C3, DIM);

    // 3) attention
    flash_h<<<dim3(SEQ / 128, BATCH * HEADS), 256, FLASH_SMEM>>>(qkvh, attn);

    // 4) x1 = x + attn @ w_proj + b_proj  (fp32 residual)
    mma_gemm_h<5,0><<<dim3(DIM / 128, TOK / 128), 256, GEMMH_SMEM>>>(
        attn, wprojT, b_proj, x, x1, TOK, DIM, DIM);

    // 5) h2 = LN2(x1)  (fp16)
    ln_h_kernel<<<TOK, 256>>>(x1, ln2_g, ln2_b, h2);

    // 6) hid = gelu(h2 @ w1 + b1)  (fp16 out)
    mma_gemm_h<3,1><<<dim3(HIDDEN / 128, TOK / 128), 256, GEMMH_SMEM>>>(
        h2, w1T, b1, nullptr, hid, TOK, HIDDEN, DIM);

    // 7) out = x1 + hid @ w2 + b2  (fp32 residual)
    mma_gemm_h<5,0><<<dim3(DIM / 128, TOK / 128), 256, GEMMH_SMEM>>>(
        hid, w2T, b2, x1, out, TOK, DIM, HIDDEN);
}

// round 14
// speedup vs baseline: 1.0610x; 1.0318x over previous
#include <cuda_runtime.h>
#include <cuda_fp16.h>
#include <cstdint>
#include <math.h>

// ---------------------------------------------------------------------------
// Problem dims
// ---------------------------------------------------------------------------
#define BATCH   2
#define SEQ     2048
#define TOK     (BATCH * SEQ)      // 4096
#define DIM     1024
#define HEADS   16
#define HD      64
#define HIDDEN  (4 * DIM)          // 4096
#define C3      (3 * DIM)          // 3072

// ---------------------------------------------------------------------------
// Scratch (device globals; no allocations allowed)
// ---------------------------------------------------------------------------
__device__ float  g_x1  [TOK * DIM];
__device__ __half g_qkvh[TOK * C3];
__device__ __half g_h1  [TOK * DIM];
__device__ __half g_h2  [TOK * DIM];
__device__ __half g_attn[TOK * DIM];
__device__ __half g_hid [TOK * HIDDEN];
__device__ __half g_wqkvh [DIM * C3];      // fp16 copies, original [K][N] layout
__device__ __half g_wprojh[DIM * DIM];
__device__ __half g_w1h   [DIM * HIDDEN];
__device__ __half g_w2h   [HIDDEN * DIM];

// ---------------------------------------------------------------------------
// Helpers
// ---------------------------------------------------------------------------
__device__ __forceinline__ uint32_t smem_u32(const void* p) {
    uint32_t a;
    asm("{ .reg .u64 t; cvta.to.shared.u64 t, %1; cvt.u32.u64 %0, t; }" : "=r"(a) : "l"(p));
    return a;
}
__device__ __forceinline__ float gelu_erf(float v) {
    return 0.5f * v * (1.0f + erff(v * 0.70710678118654752440f));
}
__device__ __forceinline__ uint32_t pack_f16x2(float a, float b) {
    uint32_t r;
    asm("cvt.rn.f16x2.f32 %0, %1, %2;" : "=r"(r) : "f"(b), "f"(a));
    return r;
}
__device__ __forceinline__ uint32_t hmul2(uint32_t a, uint32_t b) {
    uint32_t r;
    asm("mul.rn.f16x2 %0, %1, %2;" : "=r"(r) : "r"(a), "r"(b));
    return r;
}
__device__ __forceinline__ uint32_t hsub2(uint32_t a, uint32_t b) {
    uint32_t r;
    asm("sub.rn.f16x2 %0, %1, %2;" : "=r"(r) : "r"(a), "r"(b));
    return r;
}
__device__ __forceinline__ uint32_t hex2x2(uint32_t a) {
    uint32_t r;
    asm("ex2.approx.f16x2 %0, %1;" : "=r"(r) : "r"(a));
    return r;
}
__device__ __forceinline__ float ex2(float x) {
    float y;
    asm("ex2.approx.ftz.f32 %0, %1;" : "=f"(y) : "f"(x));
    return y;
}
__device__ __forceinline__ float2 unpack_h2(uint32_t u) {
    __half2 h = *reinterpret_cast<__half2*>(&u);
    return __half22float2(h);
}
__device__ __forceinline__ void mma_f16(
    float& d0, float& d1, float& d2, float& d3,
    uint32_t a0, uint32_t a1, uint32_t a2, uint32_t a3,
    uint32_t b0, uint32_t b1)
{
    asm volatile(
        "mma.sync.aligned.m16n8k16.row.col.f32.f16.f16.f32 "
        "{%0,%1,%2,%3}, {%4,%5,%6,%7}, {%8,%9}, {%0,%1,%2,%3};"
        : "+f"(d0), "+f"(d1), "+f"(d2), "+f"(d3)
        : "r"(a0), "r"(a1), "r"(a2), "r"(a3), "r"(b0), "r"(b1));
}
__device__ __forceinline__ void ldsm_x4(
    uint32_t& r0, uint32_t& r1, uint32_t& r2, uint32_t& r3, uint32_t addr)
{
    asm volatile("ldmatrix.sync.aligned.m8n8.x4.shared.b16 {%0,%1,%2,%3}, [%4];"
        : "=r"(r0), "=r"(r1), "=r"(r2), "=r"(r3) : "r"(addr));
}
__device__ __forceinline__ void ldsm_x4_t(
    uint32_t& r0, uint32_t& r1, uint32_t& r2, uint32_t& r3, uint32_t addr)
{
    asm volatile("ldmatrix.sync.aligned.m8n8.x4.trans.shared.b16 {%0,%1,%2,%3}, [%4];"
        : "=r"(r0), "=r"(r1), "=r"(r2), "=r"(r3) : "r"(addr));
}
__device__ __forceinline__ void cp_async16(uint32_t dst, const void* src) {
    asm volatile("cp.async.cg.shared.global [%0], [%1], 16;" :: "r"(dst), "l"(src));
}
#define CP_COMMIT asm volatile("cp.async.commit_group;")
template <int N>
__device__ __forceinline__ void cp_wait() {
    asm volatile("cp.async.wait_group %0;" :: "n"(N));
}

// ---------------------------------------------------------------------------
// fp16 GEMM: C = A[M,K] @ B[K,N] (B row-major!), fp32 accum. 128x128 CTA,
// 8 warps (4x2), warp 32x64, m16n8k16, BK=32, 3-stage cp.async.
// A frags via ldmatrix, B frags via ldmatrix.trans on row-major tile.
// EPI: 1=bias, 2=gelu, 4=residual.  HOUT: write fp16 (else fp32).
// ---------------------------------------------------------------------------
#define AH_ST 40                         // A row stride (halves)
#define AH_STG (128 * AH_ST)             // 5120 halves / stage
#define BH_ST 136                        // B row stride (halves): 272B == 16 mod 128
#define BH_STG (32 * BH_ST)              // 4352 halves / stage
#define GEMMH_SMEM (3 * (AH_STG + BH_STG) * 2)   // 56832 bytes

template <int EPI, int HOUT>
__global__ void __launch_bounds__(256, 2) mma_gemm_h(
    const __half* __restrict__ A, const __half* __restrict__ B,
    const float* __restrict__ bias, const float* __restrict__ R,
    void* __restrict__ Cv, int M, int N, int K)
{
    extern __shared__ __half smh[];
    __half* Asm = smh;
    __half* Bsm = smh + 3 * AH_STG;
    const uint32_t a_u32 = smem_u32(Asm);
    const uint32_t b_u32 = smem_u32(Bsm);

    const int tid = threadIdx.x;
    const int lane = tid & 31, warp = tid >> 5;
    const int wy = warp >> 1, wx = warp & 1;
    const int g = lane >> 2, t = lane & 3;
    const int lm = lane >> 3, lr = lane & 7;
    const int bm = blockIdx.y * 128, bn = blockIdx.x * 128;

    uint32_t aoff[2], boff[4];
    #pragma unroll
    for (int mf = 0; mf < 2; mf++)
        aoff[mf] = (uint32_t)(((wy * 32 + mf * 16 + (lane & 15)) * AH_ST
                               + (lane >> 4) * 8) * 2);
    // B trans-frag: rows k (within 16-block), cols n. Same pattern as flash V.
    #pragma unroll
    for (int j = 0; j < 4; j++)
        boff[j] = (uint32_t)((((lm & 1) * 8 + lr) * BH_ST
                              + wx * 64 + 16 * j + (lm >> 1) * 8) * 2);

    auto issue = [&](int s, int k0) {
        #pragma unroll
        for (int w = 0; w < 2; w++) {
            int id = w * 256 + tid;
            int r = id >> 2, c = (id & 3) << 3;
            cp_async16(a_u32 + (uint32_t)(s * AH_STG + r * AH_ST + c) * 2,
                       A + (long)(bm + r) * K + k0 + c);
        }
        #pragma unroll
        for (int w = 0; w < 2; w++) {
            int id = w * 256 + tid;
            int r = id >> 4, c = (id & 15) << 3;   // 32 rows x 128 cols
            cp_async16(b_u32 + (uint32_t)(s * BH_STG + r * BH_ST + c) * 2,
                       B + (long)(k0 + r) * N + bn + c);
        }
        CP_COMMIT;
    };

    float acc[2][8][4];
    #pragma unroll
    for (int i = 0; i < 2; i++)
        #pragma unroll
        for (int j = 0; j < 8; j++)
            #pragma unroll
            for (int e = 0; e < 4; e++) acc[i][j][e] = 0.f;

    const int NK = K >> 5;
    issue(0, 0);
    issue(1, 32);

    for (int it = 0; it < NK; ++it) {
        if (it == NK - 1) { cp_wait<0>(); } else { cp_wait<1>(); }
        __syncthreads();
        if (it + 2 < NK) issue((it + 2) % 3, (it + 2) << 5);

        const uint32_t a_st = a_u32 + (uint32_t)((it % 3) * AH_STG) * 2;
        const uint32_t b_st = b_u32 + (uint32_t)((it % 3) * BH_STG) * 2;
        #pragma unroll
        for (int k16 = 0; k16 < 32; k16 += 16) {
            uint32_t af[2][4], bf[8][2];
            #pragma unroll
            for (int mf = 0; mf < 2; mf++)
                ldsm_x4(af[mf][0], af[mf][1], af[mf][2], af[mf][3],
                        a_st + aoff[mf] + k16 * 2);
            #pragma unroll
            for (int j = 0; j < 4; j++)
                ldsm_x4_t(bf[2*j][0], bf[2*j][1], bf[2*j+1][0], bf[2*j+1][1],
                          b_st + boff[j] + (uint32_t)(k16 * BH_ST) * 2);
            #pragma unroll
            for (int mf = 0; mf < 2; mf++)
                #pragma unroll
                for (int nf = 0; nf < 8; nf++)
                    mma_f16(acc[mf][nf][0], acc[mf][nf][1],
                            acc[mf][nf][2], acc[mf][nf][3],
                            af[mf][0], af[mf][1], af[mf][2], af[mf][3],
                            bf[nf][0], bf[nf][1]);
        }
    }

    #pragma unroll
    for (int mf = 0; mf < 2; mf++) {
        const long row = bm + wy * 32 + mf * 16 + g;
        #pragma unroll
        for (int nf = 0; nf < 8; nf++) {
            const long col = bn + wx * 64 + nf * 8 + t * 2;
            float2 v0 = make_float2(acc[mf][nf][0], acc[mf][nf][1]);
            float2 v1 = make_float2(acc[mf][nf][2], acc[mf][nf][3]);
            if (EPI & 1) {
                const float2 bv = *reinterpret_cast<const float2*>(bias + col);
                v0.x += bv.x; v0.y += bv.y;
                v1.x += bv.x; v1.y += bv.y;
            }
            if (EPI & 2) {
                v0.x = gelu_erf(v0.x); v0.y = gelu_erf(v0.y);
                v1.x = gelu_erf(v1.x); v1.y = gelu_erf(v1.y);
            }
            if (EPI & 4) {
                const float2 r0 = *reinterpret_cast<const float2*>(R + row * N + col);
                const float2 r1 = *reinterpret_cast<const float2*>(R + (row + 8) * N + col);
                v0.x += r0.x; v0.y += r0.y;
                v1.x += r1.x; v1.y += r1.y;
            }
            if (HOUT) {
                __half* C = reinterpret_cast<__half*>(Cv);
                *reinterpret_cast<uint32_t*>(C + row * N + col) = pack_f16x2(v0.x, v0.y);
                *reinterpret_cast<uint32_t*>(C + (row + 8) * N + col) = pack_f16x2(v1.x, v1.y);
            } else {
                float* C = reinterpret_cast<float*>(Cv);
                *reinterpret_cast<float2*>(C + row * N + col) = v0;
                *reinterpret_cast<float2*>(C + (row + 8) * N + col) = v1;
            }
        }
    }
}

// ---------------------------------------------------------------------------
// fp16 flash attention (R13 best): 128 q-rows/CTA, 8 warps x 16 rows.
// Q (pre-scaled) in registers; 128-key staging buffers; K ldmatrix,
// V ldmatrix.trans; register-resident P; fp16x2 exp softmax.
// ---------------------------------------------------------------------------
#define KVST 72
#define KVROWS 128
#define KVBUF (KVROWS * KVST)
#define FV_OFF (2 * KVBUF)
#define FLASH_SMEM (4 * KVBUF * 2)      // 73728 bytes

__global__ void __launch_bounds__(256, 2) flash_h(
    const __half* __restrict__ qkv, __half* __restrict__ out)
{
    extern __shared__ __half smh[];
    const uint32_t k_su = smem_u32(smh);
    const uint32_t v_su = smem_u32(smh + FV_OFF);

    const int tid = threadIdx.x;
    const int lane = tid & 31, warp = tid >> 5;
    const int g = lane >> 2, t = lane & 3;
    const int lm = lane >> 3, lr = lane & 7;
    const int b = blockIdx.y >> 4, h = blockIdx.y & 15;
    const int q0 = blockIdx.x * 128;
    const int m0 = warp * 16;
    const long base = (long)b * SEQ * C3 + h * HD;

    uint32_t koff[4];
    #pragma unroll
    for (int j = 0; j < 4; j++)
        koff[j] = (uint32_t)(((j * 16 + ((lane >> 4) & 1) * 8 + (lane & 7)) * KVST
                              + ((lane >> 3) & 1) * 8) * 2);

    const float sscale = 0.125f * 1.4426950408889634f;
    const uint32_t sc2 = pack_f16x2(sscale, sscale);
    uint32_t qf[4][4];
    {
        const uint32_t* q_lo = reinterpret_cast<const uint32_t*>(
            qkv + base + (long)(q0 + m0 + g) * C3);
        const uint32_t* q_hi = reinterpret_cast<const uint32_t*>(
            qkv + base + (long)(q0 + m0 + g + 8) * C3);
        #pragma unroll
        for (int s = 0; s < 4; s++) {
            qf[s][0] = hmul2(q_lo[8 * s + t],     sc2);
            qf[s][1] = hmul2(q_hi[8 * s + t],     sc2);
            qf[s][2] = hmul2(q_lo[8 * s + t + 4], sc2);
            qf[s][3] = hmul2(q_hi[8 * s + t + 4], sc2);
        }
    }

    auto issue_kv = [&](int kt, int bf) {
        const long kb = base + (long)(kt * KVROWS) * C3;
        #pragma unroll
        for (int i = 0; i < 4; i++) {
            int id = i * 256 + tid;
            int r = id >> 3, c = (id & 7) << 3;
            cp_async16(k_su + (uint32_t)(bf * KVBUF + r * KVST + c) * 2,
                       qkv + kb + (long)r * C3 + 1024 + c);
        }
        #pragma unroll
        for (int i = 0; i < 4; i++) {
            int id = i * 256 + tid;
            int r = id >> 3, c = (id & 7) << 3;
            cp_async16(v_su + (uint32_t)(bf * KVBUF + r * KVST + c) * 2,
                       qkv + kb + (long)r * C3 + 2048 + c);
        }
        CP_COMMIT;
    };

    float Of[8][4];
    #pragma unroll
    for (int nf = 0; nf < 8; nf++)
        #pragma unroll
        for (int e = 0; e < 4; e++) Of[nf][e] = 0.f;
    float m_[2] = {-1e30f, -1e30f};
    float l_[2] = {0.f, 0.f};

    issue_kv(0, 0);

    const int NT = SEQ / KVROWS;       // 16
    for (int kt = 0; kt < NT; kt++) {
        const int buf = kt & 1;
        __syncthreads();
        if (kt + 1 < NT) { issue_kv(kt + 1, buf ^ 1); cp_wait<1>(); }
        else             { cp_wait<0>(); }
        __syncthreads();

        #pragma unroll
        for (int sub = 0; sub < 2; sub++) {
            const uint32_t k_base = k_su + (uint32_t)(buf * KVBUF + sub * 64 * KVST) * 2;
            const uint32_t v_base = v_su + (uint32_t)(buf * KVBUF + sub * 64 * KVST) * 2;

            float Sf[8][4];
            #pragma unroll
            for (int nf = 0; nf < 8; nf++)
                #pragma unroll
                for (int e = 0; e < 4; e++) Sf[nf][e] = 0.f;

            #pragma unroll
            for (int s = 0; s < 4; s++) {
                uint32_t kf[8][2];
                #pragma unroll
                for (int j = 0; j < 4; j++)
                    ldsm_x4(kf[2*j][0], kf[2*j][1], kf[2*j+1][0], kf[2*j+1][1],
                            k_base + koff[j] + s * 32);
                #pragma unroll
                for (int nf = 0; nf < 8; nf++)
                    mma_f16(Sf[nf][0], Sf[nf][1], Sf[nf][2], Sf[nf][3],
                            qf[s][0], qf[s][1], qf[s][2], qf[s][3],
                            kf[nf][0], kf[nf][1]);
            }

            // Online softmax: exp in fp16x2
            uint32_t p2_[2][8];
            #pragma unroll
            for (int r = 0; r < 2; r++) {
                const int e = r * 2;
                float mx = -1e30f;
                #pragma unroll
                for (int nf = 0; nf < 8; nf++)
                    mx = fmaxf(mx, fmaxf(Sf[nf][e], Sf[nf][e + 1]));
                mx = fmaxf(mx, __shfl_xor_sync(0xffffffffu, mx, 1));
                mx = fmaxf(mx, __shfl_xor_sync(0xffffffffu, mx, 2));
                const float nm = fmaxf(m_[r], mx);
                const float corr = ex2(m_[r] - nm);
                const uint32_t nm2 = pack_f16x2(nm, nm);
                float ps = 0.f;
                #pragma unroll
                for (int nf = 0; nf < 8; nf++) {
                    uint32_t s2 = pack_f16x2(Sf[nf][e], Sf[nf][e + 1]);
                    uint32_t p = hex2x2(hsub2(s2, nm2));
                    p2_[r][nf] = p;
                    float2 pf = unpack_h2(p);
                    ps += pf.x + pf.y;
                }
                ps += __shfl_xor_sync(0xffffffffu, ps, 1);
                ps += __shfl_xor_sync(0xffffffffu, ps, 2);
                l_[r] = l_[r] * corr + ps;
                m_[r] = nm;
                #pragma unroll
                for (int nf = 0; nf < 8; nf++) {
                    Of[nf][e] *= corr; Of[nf][e + 1] *= corr;
                }
            }

            // O += P @ V
            #pragma unroll
            for (int s = 0; s < 4; s++) {
                const uint32_t pa0 = p2_[0][2*s];
                const uint32_t pa1 = p2_[1][2*s];
                const uint32_t pa2 = p2_[0][2*s+1];
                const uint32_t pa3 = p2_[1][2*s+1];
                #pragma unroll
                for (int np = 0; np < 4; np++) {
                    uint32_t b0a, b1a, b0b, b1b;
                    const uint32_t addr = v_base +
                        (uint32_t)((16 * s + (lm & 1) * 8 + lr) * KVST + 16 * np + (lm >> 1) * 8) * 2;
                    ldsm_x4_t(b0a, b1a, b0b, b1b, addr);
                    mma_f16(Of[2*np][0],   Of[2*np][1],   Of[2*np][2],   Of[2*np][3],
                            pa0, pa1, pa2, pa3, b0a, b1a);
                    mma_f16(Of[2*np+1][0], Of[2*np+1][1], Of[2*np+1][2], Of[2*np+1][3],
                            pa0, pa1, pa2, pa3, b0b, b1b);
                }
            }
        }
    }

    #pragma unroll
    for (int r = 0; r < 2; r++) {
        const float inv = 1.0f / l_[r];
        const long row = (long)b * SEQ + q0 + m0 + g + r * 8;
        const int e = r * 2;
        #pragma unroll
        for (int nf = 0; nf < 8; nf++) {
            *reinterpret_cast<uint32_t*>(out + row * DIM + h * HD + nf * 8 + 2 * t) =
                pack_f16x2(Of[nf][e] * inv, Of[nf][e + 1] * inv);
        }
    }
}

// ---------------------------------------------------------------------------
// Streaming fp32 -> fp16 convert (no transpose)
// ---------------------------------------------------------------------------
__global__ void __launch_bounds__(256) cvt_h(
    const float* __restrict__ in, __half* __restrict__ out, int n4)
{
    int i = blockIdx.x * 256 + threadIdx.x;
    if (i < n4) {
        float4 v = reinterpret_cast<const float4*>(in)[i];
        uint2 o;
        o.x = pack_f16x2(v.x, v.y);
        o.y = pack_f16x2(v.z, v.w);
        reinterpret_cast<uint2*>(out)[i] = o;
    }
}

// ---------------------------------------------------------------------------
// LayerNorm -> fp16
// ---------------------------------------------------------------------------
__global__ void __launch_bounds__(256) ln_h_kernel(
    const float* __restrict__ x, const float* __restrict__ g,
    const float* __restrict__ b, __half* __restrict__ out)
{
    const int row = blockIdx.x;
    const int tid = threadIdx.x;
    float4 v = reinterpret_cast<const float4*>(x + (long)row * DIM)[tid];

    __shared__ float red1[8];
    __shared__ float red2[8];

    float s = v.x + v.y + v.z + v.w;
    #pragma unroll
    for (int off = 16; off; off >>= 1) s += __shfl_xor_sync(0xffffffffu, s, off);
    if ((tid & 31) == 0) red1[tid >> 5] = s;
    __syncthreads();
    float tot = 0.f;
    #pragma unroll
    for (int w = 0; w < 8; w++) tot += red1[w];
    const float mean = tot * (1.0f / DIM);

    float dx = v.x - mean, dy = v.y - mean, dz = v.z - mean, dw = v.w - mean;
    float q = dx * dx + dy * dy + dz * dz + dw * dw;
    #pragma unroll
    for (int off = 16; off; off >>= 1) q += __shfl_xor_sync(0xffffffffu, q, off);
    if ((tid & 31) == 0) red2[tid >> 5] = q;
    __syncthreads();
    float qtot = 0.f;
    #pragma unroll
    for (int w = 0; w < 8; w++) qtot += red2[w];
    const float rstd = rsqrtf(qtot * (1.0f / DIM) + 1e-5f);

    float4 gv = reinterpret_cast<const float4*>(g)[tid];
    float4 bv = reinterpret_cast<const float4*>(b)[tid];
    uint32_t* op = reinterpret_cast<uint32_t*>(out + (long)row * DIM) + 2 * tid;
    op[0] = pack_f16x2(dx * rstd * gv.x + bv.x, dy * rstd * gv.y + bv.y);
    op[1] = pack_f16x2(dz * rstd * gv.z + bv.z, dw * rstd * gv.w + bv.w);
}

// ---------------------------------------------------------------------------
// Launch
// ---------------------------------------------------------------------------
extern "C" void kernel_launch(void* const* d_in, const int* in_sizes, int n_in,
                              void* d_out, int out_size)
{
    const float* x      = (const float*)d_in[0];
    const float* ln1_g  = (const float*)d_in[1];
    const float* ln1_b  = (const float*)d_in[2];
    const float* w_qkv  = (const float*)d_in[3];
    const float* w_proj = (const float*)d_in[4];
    const float* b_proj = (const float*)d_in[5];
    const float* ln2_g  = (const float*)d_in[6];
    const float* ln2_b  = (const float*)d_in[7];
    const float* w1     = (const float*)d_in[8];
    const float* b1     = (const float*)d_in[9];
    const float* w2     = (const float*)d_in[10];
    const float* b2     = (const float*)d_in[11];
    float* out = (float*)d_out;

    float *x1;
    __half *qkvh, *h1, *h2, *attn, *hid, *wqkvh, *wprojh, *w1h, *w2h;
    cudaGetSymbolAddress((void**)&x1,     g_x1);
    cudaGetSymbolAddress((void**)&qkvh,   g_qkvh);
    cudaGetSymbolAddress((void**)&h1,     g_h1);
    cudaGetSymbolAddress((void**)&h2,     g_h2);
    cudaGetSymbolAddress((void**)&attn,   g_attn);
    cudaGetSymbolAddress((void**)&hid,    g_hid);
    cudaGetSymbolAddress((void**)&wqkvh,  g_wqkvh);
    cudaGetSymbolAddress((void**)&wprojh, g_wprojh);
    cudaGetSymbolAddress((void**)&w1h,    g_w1h);
    cudaGetSymbolAddress((void**)&w2h,    g_w2h);

    cudaFuncSetAttribute(mma_gemm_h<0,1>, cudaFuncAttributeMaxDynamicSharedMemorySize, GEMMH_SMEM);
    cudaFuncSetAttribute(mma_gemm_h<5,0>, cudaFuncAttributeMaxDynamicSharedMemorySize, GEMMH_SMEM);
    cudaFuncSetAttribute(mma_gemm_h<3,1>, cudaFuncAttributeMaxDynamicSharedMemorySize, GEMMH_SMEM);
    cudaFuncSetAttribute(flash_h,         cudaFuncAttributeMaxDynamicSharedMemorySize, FLASH_SMEM);

    // Weight fp16 conversion (layout preserved, no transpose)
    cvt_h<<<(DIM * C3 / 4 + 255) / 256,     256>>>(w_qkv,  wqkvh,  DIM * C3 / 4);
    cvt_h<<<(DIM * DIM / 4 + 255) / 256,    256>>>(w_proj, wprojh, DIM * DIM / 4);
    cvt_h<<<(DIM * HIDDEN / 4 + 255) / 256, 256>>>(w1,     w1h,    DIM * HIDDEN / 4);
    cvt_h<<<(HIDDEN * DIM / 4 + 255) / 256, 256>>>(w2,     w2h,    HIDDEN * DIM / 4);

    // 1) h1 = LN1(x)  (fp16)
    ln_h_kernel<<<TOK, 256>>>(x, ln1_g, ln1_b, h1);

    // 2) qkvh = h1 @ w_qkv  (fp16 out)
    mma_gemm_h<0,1><<<dim3(C3 / 128, TOK / 128), 256, GEMMH_SMEM>>>(
        h1, wqkvh, nullptr, nullptr, qkvh, TOK, C3, DIM);

    // 3) attention
    flash_h<<<dim3(SEQ / 128, BATCH * HEADS), 256, FLASH_SMEM>>>(qkvh, attn);

    // 4) x1 = x + attn @ w_proj + b_proj  (fp32 residual)
    mma_gemm_h<5,0><<<dim3(DIM / 128, TOK / 128), 256, GEMMH_SMEM>>>(
        attn, wprojh, b_proj, x, x1, TOK, DIM, DIM);

    // 5) h2 = LN2(x1)  (fp16)
    ln_h_kernel<<<TOK, 256>>>(x1, ln2_g, ln2_b, h2);

    // 6) hid = gelu(h2 @ w1 + b1)  (fp16 out)
    mma_gemm_h<3,1><<<dim3(HIDDEN / 128, TOK / 128), 256, GEMMH_SMEM>>>(
        h2, w1h, b1, nullptr, hid, TOK, HIDDEN, DIM);

    // 7) out = x1 + hid @ w2 + b2  (fp32 residual)
    mma_gemm_h<5,0><<<dim3(DIM / 128, TOK / 128), 256, GEMMH_SMEM>>>(
        hid, w2h, b2, x1, out, TOK, DIM, HIDDEN);
}

// round 15
// speedup vs baseline: 1.1075x; 1.0438x over previous
#include <cuda_runtime.h>
#include <cuda_fp16.h>
#include <cstdint>
#include <math.h>

// ---------------------------------------------------------------------------
// Problem dims
// ---------------------------------------------------------------------------
#define BATCH   2
#define SEQ     2048
#define TOK     (BATCH * SEQ)      // 4096
#define DIM     1024
#define HEADS   16
#define HD      64
#define HIDDEN  (4 * DIM)          // 4096
#define C3      (3 * DIM)          // 3072

// ---------------------------------------------------------------------------
// Scratch (device globals; no allocations allowed)
// ---------------------------------------------------------------------------
__device__ float  g_x1  [TOK * DIM];
__device__ __half g_qkvh[TOK * C3];
__device__ __half g_h1  [TOK * DIM];
__device__ __half g_h2  [TOK * DIM];
__device__ __half g_attn[TOK * DIM];
__device__ __half g_hid [TOK * HIDDEN];
__device__ __half g_wqkvh [DIM * C3];      // fp16 copies, original [K][N] layout
__device__ __half g_wprojh[DIM * DIM];
__device__ __half g_w1h   [DIM * HIDDEN];
__device__ __half g_w2h   [HIDDEN * DIM];

// ---------------------------------------------------------------------------
// Helpers
// ---------------------------------------------------------------------------
__device__ __forceinline__ uint32_t smem_u32(const void* p) {
    uint32_t a;
    asm("{ .reg .u64 t; cvta.to.shared.u64 t, %1; cvt.u32.u64 %0, t; }" : "=r"(a) : "l"(p));
    return a;
}
__device__ __forceinline__ float gelu_erf(float v) {
    return 0.5f * v * (1.0f + erff(v * 0.70710678118654752440f));
}
__device__ __forceinline__ uint32_t pack_f16x2(float a, float b) {
    uint32_t r;
    asm("cvt.rn.f16x2.f32 %0, %1, %2;" : "=r"(r) : "f"(b), "f"(a));
    return r;
}
__device__ __forceinline__ uint32_t hmul2(uint32_t a, uint32_t b) {
    uint32_t r;
    asm("mul.rn.f16x2 %0, %1, %2;" : "=r"(r) : "r"(a), "r"(b));
    return r;
}
__device__ __forceinline__ uint32_t hsub2(uint32_t a, uint32_t b) {
    uint32_t r;
    asm("sub.rn.f16x2 %0, %1, %2;" : "=r"(r) : "r"(a), "r"(b));
    return r;
}
__device__ __forceinline__ uint32_t hex2x2(uint32_t a) {
    uint32_t r;
    asm("ex2.approx.f16x2 %0, %1;" : "=r"(r) : "r"(a));
    return r;
}
__device__ __forceinline__ float ex2(float x) {
    float y;
    asm("ex2.approx.ftz.f32 %0, %1;" : "=f"(y) : "f"(x));
    return y;
}
__device__ __forceinline__ float2 unpack_h2(uint32_t u) {
    __half2 h = *reinterpret_cast<__half2*>(&u);
    return __half22float2(h);
}
// NOTE: no volatile — pure register op, let ptxas schedule freely
__device__ __forceinline__ void mma_f16(
    float& d0, float& d1, float& d2, float& d3,
    uint32_t a0, uint32_t a1, uint32_t a2, uint32_t a3,
    uint32_t b0, uint32_t b1)
{
    asm("mma.sync.aligned.m16n8k16.row.col.f32.f16.f16.f32 "
        "{%0,%1,%2,%3}, {%4,%5,%6,%7}, {%8,%9}, {%0,%1,%2,%3};"
        : "+f"(d0), "+f"(d1), "+f"(d2), "+f"(d3)
        : "r"(a0), "r"(a1), "r"(a2), "r"(a3), "r"(b0), "r"(b1));
}
__device__ __forceinline__ void ldsm_x4(
    uint32_t& r0, uint32_t& r1, uint32_t& r2, uint32_t& r3, uint32_t addr)
{
    asm volatile("ldmatrix.sync.aligned.m8n8.x4.shared.b16 {%0,%1,%2,%3}, [%4];"
        : "=r"(r0), "=r"(r1), "=r"(r2), "=r"(r3) : "r"(addr));
}
__device__ __forceinline__ void ldsm_x4_t(
    uint32_t& r0, uint32_t& r1, uint32_t& r2, uint32_t& r3, uint32_t addr)
{
    asm volatile("ldmatrix.sync.aligned.m8n8.x4.trans.shared.b16 {%0,%1,%2,%3}, [%4];"
        : "=r"(r0), "=r"(r1), "=r"(r2), "=r"(r3) : "r"(addr));
}
__device__ __forceinline__ void cp_async16(uint32_t dst, const void* src) {
    asm volatile("cp.async.cg.shared.global [%0], [%1], 16;" :: "r"(dst), "l"(src));
}
#define CP_COMMIT asm volatile("cp.async.commit_group;")
template <int N>
__device__ __forceinline__ void cp_wait() {
    asm volatile("cp.async.wait_group %0;" :: "n"(N));
}

// ---------------------------------------------------------------------------
// fp16 GEMM: C = A[M,K] @ B[K,N] (B row-major), fp32 accum. 128x128 CTA,
// 8 warps (4x2), warp 32x64, m16n8k16, BK=64, 3-stage cp.async.
// A frags via ldmatrix, B frags via ldmatrix.trans.
// EPI: 1=bias, 2=gelu, 4=residual.  HOUT: write fp16 (else fp32).
// ---------------------------------------------------------------------------
#define AH_ST 72                         // A row stride (halves), 64 + 8 pad
#define AH_STG (128 * AH_ST)             // 9216 halves / stage
#define BH_ST 136                        // B row stride (halves), 128 + 8 pad
#define BH_STG (64 * BH_ST)              // 8704 halves / stage
#define GEMMH_SMEM (3 * (AH_STG + BH_STG) * 2)   // 107520 bytes

template <int EPI, int HOUT>
__global__ void __launch_bounds__(256, 2) mma_gemm_h(
    const __half* __restrict__ A, const __half* __restrict__ B,
    const float* __restrict__ bias, const float* __restrict__ R,
    void* __restrict__ Cv, int M, int N, int K)
{
    extern __shared__ __half smh[];
    __half* Asm = smh;
    __half* Bsm = smh + 3 * AH_STG;
    const uint32_t a_u32 = smem_u32(Asm);
    const uint32_t b_u32 = smem_u32(Bsm);

    const int tid = threadIdx.x;
    const int lane = tid & 31, warp = tid >> 5;
    const int wy = warp >> 1, wx = warp & 1;
    const int g = lane >> 2, t = lane & 3;
    const int lm = lane >> 3, lr = lane & 7;
    const int bm = blockIdx.y * 128, bn = blockIdx.x * 128;

    uint32_t aoff[2], boff[4];
    #pragma unroll
    for (int mf = 0; mf < 2; mf++)
        aoff[mf] = (uint32_t)(((wy * 32 + mf * 16 + (lane & 15)) * AH_ST
                               + (lane >> 4) * 8) * 2);
    #pragma unroll
    for (int j = 0; j < 4; j++)
        boff[j] = (uint32_t)((((lm & 1) * 8 + lr) * BH_ST
                              + wx * 64 + 16 * j + (lm >> 1) * 8) * 2);

    auto issue = [&](int s, int k0) {
        #pragma unroll
        for (int w = 0; w < 4; w++) {
            int id = w * 256 + tid;
            int r = id >> 3, c = (id & 7) << 3;    // 128 rows x 64 halves
            cp_async16(a_u32 + (uint32_t)(s * AH_STG + r * AH_ST + c) * 2,
                       A + (long)(bm + r) * K + k0 + c);
        }
        #pragma unroll
        for (int w = 0; w < 4; w++) {
            int id = w * 256 + tid;
            int r = id >> 4, c = (id & 15) << 3;   // 64 rows x 128 halves
            cp_async16(b_u32 + (uint32_t)(s * BH_STG + r * BH_ST + c) * 2,
                       B + (long)(k0 + r) * N + bn + c);
        }
        CP_COMMIT;
    };

    float acc[2][8][4];
    #pragma unroll
    for (int i = 0; i < 2; i++)
        #pragma unroll
        for (int j = 0; j < 8; j++)
            #pragma unroll
            for (int e = 0; e < 4; e++) acc[i][j][e] = 0.f;

    const int NK = K >> 6;
    issue(0, 0);
    issue(1, 64);

    for (int it = 0; it < NK; ++it) {
        if (it == NK - 1) { cp_wait<0>(); } else { cp_wait<1>(); }
        __syncthreads();
        if (it + 2 < NK) issue((it + 2) % 3, (it + 2) << 6);

        const uint32_t a_st = a_u32 + (uint32_t)((it % 3) * AH_STG) * 2;
        const uint32_t b_st = b_u32 + (uint32_t)((it % 3) * BH_STG) * 2;
        #pragma unroll
        for (int k16 = 0; k16 < 64; k16 += 16) {
            uint32_t af[2][4], bf[8][2];
            #pragma unroll
            for (int mf = 0; mf < 2; mf++)
                ldsm_x4(af[mf][0], af[mf][1], af[mf][2], af[mf][3],
                        a_st + aoff[mf] + k16 * 2);
            #pragma unroll
            for (int j = 0; j < 4; j++)
                ldsm_x4_t(bf[2*j][0], bf[2*j][1], bf[2*j+1][0], bf[2*j+1][1],
                          b_st + boff[j] + (uint32_t)(k16 * BH_ST) * 2);
            #pragma unroll
            for (int mf = 0; mf < 2; mf++)
                #pragma unroll
                for (int nf = 0; nf < 8; nf++)
                    mma_f16(acc[mf][nf][0], acc[mf][nf][1],
                            acc[mf][nf][2], acc[mf][nf][3],
                            af[mf][0], af[mf][1], af[mf][2], af[mf][3],
                            bf[nf][0], bf[nf][1]);
        }
    }

    #pragma unroll
    for (int mf = 0; mf < 2; mf++) {
        const long row = bm + wy * 32 + mf * 16 + g;
        #pragma unroll
        for (int nf = 0; nf < 8; nf++) {
            const long col = bn + wx * 64 + nf * 8 + t * 2;
            float2 v0 = make_float2(acc[mf][nf][0], acc[mf][nf][1]);
            float2 v1 = make_float2(acc[mf][nf][2], acc[mf][nf][3]);
            if (EPI & 1) {
                const float2 bv = *reinterpret_cast<const float2*>(bias + col);
                v0.x += bv.x; v0.y += bv.y;
                v1.x += bv.x; v1.y += bv.y;
            }
            if (EPI & 2) {
                v0.x = gelu_erf(v0.x); v0.y = gelu_erf(v0.y);
                v1.x = gelu_erf(v1.x); v1.y = gelu_erf(v1.y);
            }
            if (EPI & 4) {
                const float2 r0 = *reinterpret_cast<const float2*>(R + row * N + col);
                const float2 r1 = *reinterpret_cast<const float2*>(R + (row + 8) * N + col);
                v0.x += r0.x; v0.y += r0.y;
                v1.x += r1.x; v1.y += r1.y;
            }
            if (HOUT) {
                __half* C = reinterpret_cast<__half*>(Cv);
                *reinterpret_cast<uint32_t*>(C + row * N + col) = pack_f16x2(v0.x, v0.y);
                *reinterpret_cast<uint32_t*>(C + (row + 8) * N + col) = pack_f16x2(v1.x, v1.y);
            } else {
                float* C = reinterpret_cast<float*>(Cv);
                *reinterpret_cast<float2*>(C + row * N + col) = v0;
                *reinterpret_cast<float2*>(C + (row + 8) * N + col) = v1;
            }
        }
    }
}

// ---------------------------------------------------------------------------
// fp16 flash attention (R13/R14 best): 128 q-rows/CTA, 8 warps x 16 rows.
// Q (pre-scaled) in registers; 128-key staging; K ldmatrix, V ldmatrix.trans;
// register-resident P; fp16x2 exp softmax.
// ---------------------------------------------------------------------------
#define KVST 72
#define KVROWS 128
#define KVBUF (KVROWS * KVST)
#define FV_OFF (2 * KVBUF)
#define FLASH_SMEM (4 * KVBUF * 2)      // 73728 bytes

__global__ void __launch_bounds__(256, 2) flash_h(
    const __half* __restrict__ qkv, __half* __restrict__ out)
{
    extern __shared__ __half smh[];
    const uint32_t k_su = smem_u32(smh);
    const uint32_t v_su = smem_u32(smh + FV_OFF);

    const int tid = threadIdx.x;
    const int lane = tid & 31, warp = tid >> 5;
    const int g = lane >> 2, t = lane & 3;
    const int lm = lane >> 3, lr = lane & 7;
    const int b = blockIdx.y >> 4, h = blockIdx.y & 15;
    const int q0 = blockIdx.x * 128;
    const int m0 = warp * 16;
    const long base = (long)b * SEQ * C3 + h * HD;

    uint32_t koff[4];
    #pragma unroll
    for (int j = 0; j < 4; j++)
        koff[j] = (uint32_t)(((j * 16 + ((lane >> 4) & 1) * 8 + (lane & 7)) * KVST
                              + ((lane >> 3) & 1) * 8) * 2);

    const float sscale = 0.125f * 1.4426950408889634f;
    const uint32_t sc2 = pack_f16x2(sscale, sscale);
    uint32_t qf[4][4];
    {
        const uint32_t* q_lo = reinterpret_cast<const uint32_t*>(
            qkv + base + (long)(q0 + m0 + g) * C3);
        const uint32_t* q_hi = reinterpret_cast<const uint32_t*>(
            qkv + base + (long)(q0 + m0 + g + 8) * C3);
        #pragma unroll
        for (int s = 0; s < 4; s++) {
            qf[s][0] = hmul2(q_lo[8 * s + t],     sc2);
            qf[s][1] = hmul2(q_hi[8 * s + t],     sc2);
            qf[s][2] = hmul2(q_lo[8 * s + t + 4], sc2);
            qf[s][3] = hmul2(q_hi[8 * s + t + 4], sc2);
        }
    }

    auto issue_kv = [&](int kt, int bf) {
        const long kb = base + (long)(kt * KVROWS) * C3;
        #pragma unroll
        for (int i = 0; i < 4; i++) {
            int id = i * 256 + tid;
            int r = id >> 3, c = (id & 7) << 3;
            cp_async16(k_su + (uint32_t)(bf * KVBUF + r * KVST + c) * 2,
                       qkv + kb + (long)r * C3 + 1024 + c);
        }
        #pragma unroll
        for (int i = 0; i < 4; i++) {
            int id = i * 256 + tid;
            int r = id >> 3, c = (id & 7) << 3;
            cp_async16(v_su + (uint32_t)(bf * KVBUF + r * KVST + c) * 2,
                       qkv + kb + (long)r * C3 + 2048 + c);
        }
        CP_COMMIT;
    };

    float Of[8][4];
    #pragma unroll
    for (int nf = 0; nf < 8; nf++)
        #pragma unroll
        for (int e = 0; e < 4; e++) Of[nf][e] = 0.f;
    float m_[2] = {-1e30f, -1e30f};
    float l_[2] = {0.f, 0.f};

    issue_kv(0, 0);

    const int NT = SEQ / KVROWS;       // 16
    for (int kt = 0; kt < NT; kt++) {
        const int buf = kt & 1;
        __syncthreads();
        if (kt + 1 < NT) { issue_kv(kt + 1, buf ^ 1); cp_wait<1>(); }
        else             { cp_wait<0>(); }
        __syncthreads();

        #pragma unroll
        for (int sub = 0; sub < 2; sub++) {
            const uint32_t k_base = k_su + (uint32_t)(buf * KVBUF + sub * 64 * KVST) * 2;
            const uint32_t v_base = v_su + (uint32_t)(buf * KVBUF + sub * 64 * KVST) * 2;

            float Sf[8][4];
            #pragma unroll
            for (int nf = 0; nf < 8; nf++)
                #pragma unroll
                for (int e = 0; e < 4; e++) Sf[nf][e] = 0.f;

            #pragma unroll
            for (int s = 0; s < 4; s++) {
                uint32_t kf[8][2];
                #pragma unroll
                for (int j = 0; j < 4; j++)
                    ldsm_x4(kf[2*j][0], kf[2*j][1], kf[2*j+1][0], kf[2*j+1][1],
                            k_base + koff[j] + s * 32);
                #pragma unroll
                for (int nf = 0; nf < 8; nf++)
                    mma_f16(Sf[nf][0], Sf[nf][1], Sf[nf][2], Sf[nf][3],
                            qf[s][0], qf[s][1], qf[s][2], qf[s][3],
                            kf[nf][0], kf[nf][1]);
            }

            // Online softmax: exp in fp16x2
            uint32_t p2_[2][8];
            #pragma unroll
            for (int r = 0; r < 2; r++) {
                const int e = r * 2;
                float mx = -1e30f;
                #pragma unroll
                for (int nf = 0; nf < 8; nf++)
                    mx = fmaxf(mx, fmaxf(Sf[nf][e], Sf[nf][e + 1]));
                mx = fmaxf(mx, __shfl_xor_sync(0xffffffffu, mx, 1));
                mx = fmaxf(mx, __shfl_xor_sync(0xffffffffu, mx, 2));
                const float nm = fmaxf(m_[r], mx);
                const float corr = ex2(m_[r] - nm);
                const uint32_t nm2 = pack_f16x2(nm, nm);
                float ps = 0.f;
                #pragma unroll
                for (int nf = 0; nf < 8; nf++) {
                    uint32_t s2 = pack_f16x2(Sf[nf][e], Sf[nf][e + 1]);
                    uint32_t p = hex2x2(hsub2(s2, nm2));
                    p2_[r][nf] = p;
                    float2 pf = unpack_h2(p);
                    ps += pf.x + pf.y;
                }
                ps += __shfl_xor_sync(0xffffffffu, ps, 1);
                ps += __shfl_xor_sync(0xffffffffu, ps, 2);
                l_[r] = l_[r] * corr + ps;
                m_[r] = nm;
                #pragma unroll
                for (int nf = 0; nf < 8; nf++) {
                    Of[nf][e] *= corr; Of[nf][e + 1] *= corr;
                }
            }

            // O += P @ V
            #pragma unroll
            for (int s = 0; s < 4; s++) {
                const uint32_t pa0 = p2_[0][2*s];
                const uint32_t pa1 = p2_[1][2*s];
                const uint32_t pa2 = p2_[0][2*s+1];
                const uint32_t pa3 = p2_[1][2*s+1];
                #pragma unroll
                for (int np = 0; np < 4; np++) {
                    uint32_t b0a, b1a, b0b, b1b;
                    const uint32_t addr = v_base +
                        (uint32_t)((16 * s + (lm & 1) * 8 + lr) * KVST + 16 * np + (lm >> 1) * 8) * 2;
                    ldsm_x4_t(b0a, b1a, b0b, b1b, addr);
                    mma_f16(Of[2*np][0],   Of[2*np][1],   Of[2*np][2],   Of[2*np][3],
                            pa0, pa1, pa2, pa3, b0a, b1a);
                    mma_f16(Of[2*np+1][0], Of[2*np+1][1], Of[2*np+1][2], Of[2*np+1][3],
                            pa0, pa1, pa2, pa3, b0b, b1b);
                }
            }
        }
    }

    #pragma unroll
    for (int r = 0; r < 2; r++) {
        const float inv = 1.0f / l_[r];
        const long row = (long)b * SEQ + q0 + m0 + g + r * 8;
        const int e = r * 2;
        #pragma unroll
        for (int nf = 0; nf < 8; nf++) {
            *reinterpret_cast<uint32_t*>(out + row * DIM + h * HD + nf * 8 + 2 * t) =
                pack_f16x2(Of[nf][e] * inv, Of[nf][e + 1] * inv);
        }
    }
}

// ---------------------------------------------------------------------------
// Fused fp32 -> fp16 convert of all four weight matrices (one launch)
// Segments (in float4 quads): wqkv, wproj, w1, w2
// ---------------------------------------------------------------------------
#define Q_WQKV  (DIM * C3 / 4)          // 786432
#define Q_WPROJ (DIM * DIM / 4)         // 262144
#define Q_W1    (DIM * HIDDEN / 4)      // 1048576
#define Q_W2    (HIDDEN * DIM / 4)      // 1048576
#define Q_TOTAL (Q_WQKV + Q_WPROJ + Q_W1 + Q_W2)

__global__ void __launch_bounds__(256) cvt_all(
    const float* __restrict__ wqkv, const float* __restrict__ wproj,
    const float* __restrict__ w1,   const float* __restrict__ w2,
    __half* __restrict__ oqkv, __half* __restrict__ oproj,
    __half* __restrict__ o1,   __half* __restrict__ o2)
{
    int i = blockIdx.x * 256 + threadIdx.x;
    if (i >= Q_TOTAL) return;
    const float* in;
    __half* out;
    if (i < Q_WQKV)                       { in = wqkv;  out = oqkv; }
    else if ((i -= Q_WQKV) < Q_WPROJ)     { in = wproj; out = oproj; }
    else if ((i -= Q_WPROJ) < Q_W1)       { in = w1;    out = o1; }
    else { i -= Q_W1;                       in = w2;    out = o2; }
    float4 v = reinterpret_cast<const float4*>(in)[i];
    uint2 o;
    o.x = pack_f16x2(v.x, v.y);
    o.y = pack_f16x2(v.z, v.w);
    reinterpret_cast<uint2*>(out)[i] = o;
}

// ---------------------------------------------------------------------------
// LayerNorm -> fp16
// ---------------------------------------------------------------------------
__global__ void __launch_bounds__(256) ln_h_kernel(
    const float* __restrict__ x, const float* __restrict__ g,
    const float* __restrict__ b, __half* __restrict__ out)
{
    const int row = blockIdx.x;
    const int tid = threadIdx.x;
    float4 v = reinterpret_cast<const float4*>(x + (long)row * DIM)[tid];

    __shared__ float red1[8];
    __shared__ float red2[8];

    float s = v.x + v.y + v.z + v.w;
    #pragma unroll
    for (int off = 16; off; off >>= 1) s += __shfl_xor_sync(0xffffffffu, s, off);
    if ((tid & 31) == 0) red1[tid >> 5] = s;
    __syncthreads();
    float tot = 0.f;
    #pragma unroll
    for (int w = 0; w < 8; w++) tot += red1[w];
    const float mean = tot * (1.0f / DIM);

    float dx = v.x - mean, dy = v.y - mean, dz = v.z - mean, dw = v.w - mean;
    float q = dx * dx + dy * dy + dz * dz + dw * dw;
    #pragma unroll
    for (int off = 16; off; off >>= 1) q += __shfl_xor_sync(0xffffffffu, q, off);
    if ((tid & 31) == 0) red2[tid >> 5] = q;
    __syncthreads();
    float qtot = 0.f;
    #pragma unroll
    for (int w = 0; w < 8; w++) qtot += red2[w];
    const float rstd = rsqrtf(qtot * (1.0f / DIM) + 1e-5f);

    float4 gv = reinterpret_cast<const float4*>(g)[tid];
    float4 bv = reinterpret_cast<const float4*>(b)[tid];
    uint32_t* op = reinterpret_cast<uint32_t*>(out + (long)row * DIM) + 2 * tid;
    op[0] = pack_f16x2(dx * rstd * gv.x + bv.x, dy * rstd * gv.y + bv.y);
    op[1] = pack_f16x2(dz * rstd * gv.z + bv.z, dw * rstd * gv.w + bv.w);
}

// ---------------------------------------------------------------------------
// Launch
// ---------------------------------------------------------------------------
extern "C" void kernel_launch(void* const* d_in, const int* in_sizes, int n_in,
                              void* d_out, int out_size)
{
    const float* x      = (const float*)d_in[0];
    const float* ln1_g  = (const float*)d_in[1];
    const float* ln1_b  = (const float*)d_in[2];
    const float* w_qkv  = (const float*)d_in[3];
    const float* w_proj = (const float*)d_in[4];
    const float* b_proj = (const float*)d_in[5];
    const float* ln2_g  = (const float*)d_in[6];
    const float* ln2_b  = (const float*)d_in[7];
    const float* w1     = (const float*)d_in[8];
    const float* b1     = (const float*)d_in[9];
    const float* w2     = (const float*)d_in[10];
    const float* b2     = (const float*)d_in[11];
    float* out = (float*)d_out;

    float *x1;
    __half *qkvh, *h1, *h2, *attn, *hid, *wqkvh, *wprojh, *w1h, *w2h;
    cudaGetSymbolAddress((void**)&x1,     g_x1);
    cudaGetSymbolAddress((void**)&qkvh,   g_qkvh);
    cudaGetSymbolAddress((void**)&h1,     g_h1);
    cudaGetSymbolAddress((void**)&h2,     g_h2);
    cudaGetSymbolAddress((void**)&attn,   g_attn);
    cudaGetSymbolAddress((void**)&hid,    g_hid);
    cudaGetSymbolAddress((void**)&wqkvh,  g_wqkvh);
    cudaGetSymbolAddress((void**)&wprojh, g_wprojh);
    cudaGetSymbolAddress((void**)&w1h,    g_w1h);
    cudaGetSymbolAddress((void**)&w2h,    g_w2h);

    cudaFuncSetAttribute(mma_gemm_h<0,1>, cudaFuncAttributeMaxDynamicSharedMemorySize, GEMMH_SMEM);
    cudaFuncSetAttribute(mma_gemm_h<5,0>, cudaFuncAttributeMaxDynamicSharedMemorySize, GEMMH_SMEM);
    cudaFuncSetAttribute(mma_gemm_h<3,1>, cudaFuncAttributeMaxDynamicSharedMemorySize, GEMMH_SMEM);
    cudaFuncSetAttribute(flash_h,         cudaFuncAttributeMaxDynamicSharedMemorySize, FLASH_SMEM);

    // Weight fp16 conversion (all four, one launch)
    cvt_all<<<(Q_TOTAL + 255) / 256, 256>>>(
        w_qkv, w_proj, w1, w2, wqkvh, wprojh, w1h, w2h);

    // 1) h1 = LN1(x)  (fp16)
    ln_h_kernel<<<TOK, 256>>>(x, ln1_g, ln1_b, h1);

    // 2) qkvh = h1 @ w_qkv  (fp16 out)
    mma_gemm_h<0,1><<<dim3(C3 / 128, TOK / 128), 256, GEMMH_SMEM>>>(
        h1, wqkvh, nullptr, nullptr, qkvh, TOK, C3, DIM);

    // 3) attention
    flash_h<<<dim3(SEQ / 128, BATCH * HEADS), 256, FLASH_SMEM>>>(qkvh, attn);

    // 4) x1 = x + attn @ w_proj + b_proj  (fp32 residual)
    mma_gemm_h<5,0><<<dim3(DIM / 128, TOK / 128), 256, GEMMH_SMEM>>>(
        attn, wprojh, b_proj, x, x1, TOK, DIM, DIM);

    // 5) h2 = LN2(x1)  (fp16)
    ln_h_kernel<<<TOK, 256>>>(x1, ln2_g, ln2_b, h2);

    // 6) hid = gelu(h2 @ w1 + b1)  (fp16 out)
    mma_gemm_h<3,1><<<dim3(HIDDEN / 128, TOK / 128), 256, GEMMH_SMEM>>>(
        h2, w1h, b1, nullptr, hid, TOK, HIDDEN, DIM);

    // 7) out = x1 + hid @ w2 + b2  (fp32 residual)
    mma_gemm_h<5,0><<<dim3(DIM / 128, TOK / 128), 256, GEMMH_SMEM>>>(
        hid, w2h, b2, x1, out, TOK, DIM, HIDDEN);
}